// round 1
// baseline (speedup 1.0000x reference)
#include <cuda_runtime.h>
#include <cuda_bf16.h>
#include <cstdint>

// Problem constants
#define N_DIM 256
#define L_DIM 2048
#define B_DIM 128
#define CHK   128
#define NCHUNK 16   // L / CHK

// Scratch (device globals: allocation-free per harness rules)
__device__ float g_P[CHK + 1][N_DIM][N_DIM];   // g_P[p] = dA^p, p = 1..128  (~33 MB)
__device__ float g_K[CHK][N_DIM];              // g_K[k] = dA^k dB
__device__ float g_X[NCHUNK][B_DIM][N_DIM];    // chunk-end states X_j

// ---------------------------------------------------------------------------
// packed fp32x2 FMA (sm_100+): doubles FFMA throughput vs FFMA-3reg (rt 2)
// ---------------------------------------------------------------------------
__device__ __forceinline__ void ffma2(float2& c, float2 a, float2 b) {
    asm("{\n\t"
        ".reg .b64 ra, rb, rc;\n\t"
        "mov.b64 ra, {%2, %3};\n\t"
        "mov.b64 rb, {%4, %5};\n\t"
        "mov.b64 rc, {%0, %1};\n\t"
        "fma.rn.f32x2 rc, ra, rb, rc;\n\t"
        "mov.b64 {%0, %1}, rc;\n\t"
        "}"
        : "+f"(c.x), "+f"(c.y)
        : "f"(a.x), "f"(a.y), "f"(b.x), "f"(b.y));
}

// Shared micro-kernel: 64x64 output tile, 16-deep K slice.
// Ast[kk][row] (A transposed in smem), Bs[kk][col]. 256 threads, 4x4/thread.
__device__ __forceinline__ void mm_compute(const float (*Ast)[68], const float (*Bs)[66],
                                           float2 acc[4][2], int ty, int tx) {
#pragma unroll
    for (int kk = 0; kk < 16; kk++) {
        float2 b0 = *reinterpret_cast<const float2*>(&Bs[kk][tx * 4]);
        float2 b1 = *reinterpret_cast<const float2*>(&Bs[kk][tx * 4 + 2]);
#pragma unroll
        for (int ii = 0; ii < 4; ii++) {
            float a = Ast[kk][ty * 4 + ii];
            float2 a2 = make_float2(a, a);
            ffma2(acc[ii][0], a2, b0);
            ffma2(acc[ii][1], a2, b1);
        }
    }
}

// ---------------------------------------------------------------------------
// init: P[1] = dA, K[0] = dB
// ---------------------------------------------------------------------------
__global__ void k_init(const float* __restrict__ dA, const float* __restrict__ dB) {
    int idx = blockIdx.x * 256 + threadIdx.x;
    if (idx < N_DIM * N_DIM) (&g_P[1][0][0])[idx] = dA[idx];
    if (idx < N_DIM) g_K[0][idx] = dB[idx];
}

// ---------------------------------------------------------------------------
// power doubling: P[m+j] = P[j] @ P[m], j = 1..m   (NN GEMM, 256^3 each)
// grid (4, 4, m), block 256
// ---------------------------------------------------------------------------
__global__ void k_power(int m) {
    int j = blockIdx.z + 1;
    const float* __restrict__ A = &g_P[j][0][0];
    const float* __restrict__ B = &g_P[m][0][0];
    float* __restrict__ C = &g_P[m + j][0][0];

    __shared__ float Ast[16][68];
    __shared__ float Bs[16][66];
    int tid = threadIdx.x, tx = tid & 15, ty = tid >> 4;
    int row0 = blockIdx.y * 64, col0 = blockIdx.x * 64;
    float2 acc[4][2] = {};

    for (int k0 = 0; k0 < N_DIM; k0 += 16) {
#pragma unroll
        for (int p = 0; p < 4; p++) {
            int idx = p * 256 + tid;
            int r = idx >> 4, kk = idx & 15;
            Ast[kk][r] = A[(row0 + r) * N_DIM + k0 + kk];
        }
#pragma unroll
        for (int p = 0; p < 4; p++) {
            int idx = p * 256 + tid;
            int kk = idx >> 6, c = idx & 63;
            Bs[kk][c] = B[(k0 + kk) * N_DIM + col0 + c];
        }
        __syncthreads();
        mm_compute(Ast, Bs, acc, ty, tx);
        __syncthreads();
    }
#pragma unroll
    for (int ii = 0; ii < 4; ii++) {
        float4 v = make_float4(acc[ii][0].x, acc[ii][0].y, acc[ii][1].x, acc[ii][1].y);
        *reinterpret_cast<float4*>(&C[(row0 + ty * 4 + ii) * N_DIM + col0 + tx * 4]) = v;
    }
}

// ---------------------------------------------------------------------------
// K[k] = P[k] @ dB, k = 1..127.  grid 127, block 256 (thread = output i)
// ---------------------------------------------------------------------------
__global__ void k_kvec(const float* __restrict__ dB) {
    __shared__ float sb[N_DIM];
    int k = blockIdx.x + 1;
    int i = threadIdx.x;
    sb[i] = dB[i];
    __syncthreads();
    const float4* row4 = reinterpret_cast<const float4*>(&g_P[k][i][0]);
    const float4* sb4 = reinterpret_cast<const float4*>(sb);
    float acc = 0.0f;
#pragma unroll 8
    for (int j = 0; j < N_DIM / 4; j++) {
        float4 a = row4[j], b = sb4[j];
        acc += a.x * b.x + a.y * b.y + a.z * b.z + a.w * b.w;
    }
    g_K[k][i] = acc;
}

// ---------------------------------------------------------------------------
// local convolution (zero-init state per chunk):
//   out[t0+r, b, i] = sum_{s<=r} K[r-s][i] * u[t0+s, b]
// GEMM view per (chunk, r): rows=b (Toeplitz slice of u), K-dim = conv lag.
// grid (4 itile, 256 rowtile [r, bhalf], 16 chunk), block 256
// ---------------------------------------------------------------------------
__global__ void k_conv(const float* __restrict__ u, float* __restrict__ out) {
    int chunk = blockIdx.z;
    int rt = blockIdx.y;
    int r = rt >> 1;
    int b0 = (rt & 1) * 64;
    int i0 = blockIdx.x * 64;
    int t0 = chunk * CHK;

    __shared__ float Ast[16][68];   // [lag kk][b']  = u[t0 + r - kk, b]
    __shared__ float Bs[16][66];    // [lag kk][i']  = K[kk][i]
    int tid = threadIdx.x, tx = tid & 15, ty = tid >> 4;
    float2 acc[4][2] = {};

    for (int k0 = 0; k0 <= r; k0 += 16) {
#pragma unroll
        for (int p = 0; p < 4; p++) {
            int idx = p * 256 + tid;
            int kk = idx >> 6, bb = idx & 63;
            int kg = k0 + kk;
            Ast[kk][bb] = (kg <= r) ? u[(t0 + r - kg) * B_DIM + b0 + bb] : 0.0f;
        }
#pragma unroll
        for (int p = 0; p < 4; p++) {
            int idx = p * 256 + tid;
            int kk = idx >> 6, ii = idx & 63;
            Bs[kk][ii] = g_K[k0 + kk][i0 + ii];
        }
        __syncthreads();
        mm_compute(Ast, Bs, acc, ty, tx);
        __syncthreads();
    }
    int t = t0 + r;
#pragma unroll
    for (int ii = 0; ii < 4; ii++) {
        size_t off = ((size_t)t * B_DIM + b0 + ty * 4 + ii) * N_DIM + i0 + tx * 4;
        float4 v = make_float4(acc[ii][0].x, acc[ii][0].y, acc[ii][1].x, acc[ii][1].y);
        *reinterpret_cast<float4*>(out + off) = v;
    }
}

// ---------------------------------------------------------------------------
// X_0 = local output at t = 127
// ---------------------------------------------------------------------------
__global__ void k_copyx0(const float* __restrict__ out) {
    int idx = blockIdx.x * 256 + threadIdx.x;   // 32768 elems
    int b = idx >> 8, i = idx & 255;
    g_X[0][b][i] = out[((size_t)(CHK - 1) * B_DIM + b) * N_DIM + i];
}

// ---------------------------------------------------------------------------
// chunk scan step: X_j = E_j + X_{j-1} @ P[128]^T    (E_j read from d_out)
// grid (4, 2), block 256
// ---------------------------------------------------------------------------
__global__ void k_scan(const float* __restrict__ out, int j) {
    int b0 = blockIdx.y * 64, i0 = blockIdx.x * 64;
    const float* __restrict__ A = &g_X[j - 1][0][0];
    const float* __restrict__ B = &g_P[CHK][0][0];

    __shared__ float Ast[16][68];
    __shared__ float Bs[16][66];
    int tid = threadIdx.x, tx = tid & 15, ty = tid >> 4;
    float2 acc[4][2] = {};

    for (int k0 = 0; k0 < N_DIM; k0 += 16) {
#pragma unroll
        for (int p = 0; p < 4; p++) {
            int idx = p * 256 + tid;
            int r = idx >> 4, kk = idx & 15;
            Ast[kk][r] = A[(b0 + r) * N_DIM + k0 + kk];
        }
#pragma unroll
        for (int p = 0; p < 4; p++) {
            int idx = p * 256 + tid;
            int ii = idx >> 4, kk = idx & 15;
            Bs[kk][ii] = B[(i0 + ii) * N_DIM + k0 + kk];
        }
        __syncthreads();
        mm_compute(Ast, Bs, acc, ty, tx);
        __syncthreads();
    }
    int t = j * CHK + CHK - 1;
#pragma unroll
    for (int ii = 0; ii < 4; ii++) {
        int b = b0 + ty * 4 + ii;
        const float4 e = *reinterpret_cast<const float4*>(
            out + ((size_t)t * B_DIM + b) * N_DIM + i0 + tx * 4);
        float4 v = make_float4(e.x + acc[ii][0].x, e.y + acc[ii][0].y,
                               e.z + acc[ii][1].x, e.w + acc[ii][1].y);
        *reinterpret_cast<float4*>(&g_X[j][b][i0 + tx * 4]) = v;
    }
}

// ---------------------------------------------------------------------------
// correction: out[(jj+1)*CHK + r, b, :] += X_jj[b, :] @ P[r+1]^T
// grid (4 itile, 30 rowtile over (jj,b), 128 r), block 256
// ---------------------------------------------------------------------------
__global__ void k_corr(float* __restrict__ out) {
    int r = blockIdx.z;
    int grow0 = blockIdx.y * 64;
    int jj = grow0 >> 7;        // X index; target chunk = jj + 1
    int b0 = grow0 & 127;
    int i0 = blockIdx.x * 64;
    const float* __restrict__ A = &g_X[jj][0][0];
    const float* __restrict__ B = &g_P[r + 1][0][0];

    __shared__ float Ast[16][68];
    __shared__ float Bs[16][66];
    int tid = threadIdx.x, tx = tid & 15, ty = tid >> 4;
    float2 acc[4][2] = {};

    for (int k0 = 0; k0 < N_DIM; k0 += 16) {
#pragma unroll
        for (int p = 0; p < 4; p++) {
            int idx = p * 256 + tid;
            int rr = idx >> 4, kk = idx & 15;
            Ast[kk][rr] = A[(b0 + rr) * N_DIM + k0 + kk];
        }
#pragma unroll
        for (int p = 0; p < 4; p++) {
            int idx = p * 256 + tid;
            int ii = idx >> 4, kk = idx & 15;
            Bs[kk][ii] = B[(i0 + ii) * N_DIM + k0 + kk];
        }
        __syncthreads();
        mm_compute(Ast, Bs, acc, ty, tx);
        __syncthreads();
    }
    int t = (jj + 1) * CHK + r;
#pragma unroll
    for (int ii = 0; ii < 4; ii++) {
        size_t off = ((size_t)t * B_DIM + b0 + ty * 4 + ii) * N_DIM + i0 + tx * 4;
        float4 y = *reinterpret_cast<float4*>(out + off);
        y.x += acc[ii][0].x; y.y += acc[ii][0].y;
        y.z += acc[ii][1].x; y.w += acc[ii][1].y;
        *reinterpret_cast<float4*>(out + off) = y;
    }
}

// ---------------------------------------------------------------------------
extern "C" void kernel_launch(void* const* d_in, const int* in_sizes, int n_in,
                              void* d_out, int out_size) {
    const float* u  = (const float*)d_in[0];   // [L, B]
    const float* dA = (const float*)d_in[1];   // [N, N]
    const float* dB = (const float*)d_in[2];   // [N]
    float* out = (float*)d_out;                // [L, B, N]

    k_init<<<256, 256>>>(dA, dB);
    for (int m = 1; m < CHK; m <<= 1)
        k_power<<<dim3(4, 4, m), 256>>>(m);
    k_kvec<<<CHK - 1, 256>>>(dB);
    k_conv<<<dim3(4, 256, NCHUNK), 256>>>(u, out);
    k_copyx0<<<128, 256>>>(out);
    for (int j = 1; j < NCHUNK; j++)
        k_scan<<<dim3(4, 2), 256>>>(out, j);
    k_corr<<<dim3(4, 30, CHK), 256>>>(out);
}

// round 3
// speedup vs baseline: 2.1512x; 2.1512x over previous
#include <cuda_runtime.h>
#include <cuda_bf16.h>
#include <cstdint>

// Problem constants
#define N_DIM 256
#define L_DIM 2048
#define B_DIM 128
#define CHK   128
#define NCHUNK 16

// ---------------------------------------------------------------------------
// Device global scratch (allocation-free rules)
// ---------------------------------------------------------------------------
__device__ float g_P[CHK + 1][N_DIM][N_DIM];        // dA^p, p = 1..128
__device__ float g_K[CHK][N_DIM];                   // Kvec[k] = dA^k dB
__device__ float g_E[NCHUNK][B_DIM][N_DIM];         // chunk-end conv values
// bf16 hi/lo split operands for tensor cores
__device__ __nv_bfloat16 g_Ph[CHK + 1][N_DIM][N_DIM];
__device__ __nv_bfloat16 g_Pl[CHK + 1][N_DIM][N_DIM];
__device__ __nv_bfloat16 g_KTh[N_DIM][CHK];
__device__ __nv_bfloat16 g_KTl[N_DIM][CHK];
__device__ __nv_bfloat16 g_uRh[NCHUNK][B_DIM][256]; // reversed padded u windows
__device__ __nv_bfloat16 g_uRl[NCHUNK][B_DIM][256];
__device__ __nv_bfloat16 g_Xh[NCHUNK][B_DIM][N_DIM]; // g_X*[c] = X_{c-1}; [0]=0
__device__ __nv_bfloat16 g_Xl[NCHUNK][B_DIM][N_DIM];

// ---------------------------------------------------------------------------
// helpers
// ---------------------------------------------------------------------------
__device__ __forceinline__ void ffma2(float2& c, float2 a, float2 b) {
    asm("{\n\t"
        ".reg .b64 ra, rb, rc;\n\t"
        "mov.b64 ra, {%2, %3};\n\t"
        "mov.b64 rb, {%4, %5};\n\t"
        "mov.b64 rc, {%0, %1};\n\t"
        "fma.rn.f32x2 rc, ra, rb, rc;\n\t"
        "mov.b64 {%0, %1}, rc;\n\t"
        "}"
        : "+f"(c.x), "+f"(c.y)
        : "f"(a.x), "f"(a.y), "f"(b.x), "f"(b.y));
}

__device__ __forceinline__ void split_bf16(float x, __nv_bfloat16& h, __nv_bfloat16& l) {
    h = __float2bfloat16(x);
    l = __float2bfloat16(x - __bfloat162float(h));
}

// legacy tensor-core mma: D(16x8,f32) += A(16x16,bf16,row) * B(16x8,bf16,col)
__device__ __forceinline__ void mma_bf16(float d[4], const uint32_t a[4],
                                         uint32_t b0, uint32_t b1) {
    asm volatile(
        "mma.sync.aligned.m16n8k16.row.col.f32.bf16.bf16.f32 "
        "{%0,%1,%2,%3}, {%4,%5,%6,%7}, {%8,%9}, {%0,%1,%2,%3};"
        : "+f"(d[0]), "+f"(d[1]), "+f"(d[2]), "+f"(d[3])
        : "r"(a[0]), "r"(a[1]), "r"(a[2]), "r"(a[3]), "r"(b0), "r"(b1));
}

// ---------------------------------------------------------------------------
// fp32 64x64 micro-kernel (setup GEMMs)
// ---------------------------------------------------------------------------
__device__ __forceinline__ void mm_compute(const float (*Ast)[68], const float (*Bs)[66],
                                           float2 acc[4][2], int ty, int tx) {
#pragma unroll
    for (int kk = 0; kk < 16; kk++) {
        float2 b0 = *reinterpret_cast<const float2*>(&Bs[kk][tx * 4]);
        float2 b1 = *reinterpret_cast<const float2*>(&Bs[kk][tx * 4 + 2]);
#pragma unroll
        for (int ii = 0; ii < 4; ii++) {
            float a = Ast[kk][ty * 4 + ii];
            float2 a2 = make_float2(a, a);
            ffma2(acc[ii][0], a2, b0);
            ffma2(acc[ii][1], a2, b1);
        }
    }
}

// ---------------------------------------------------------------------------
// init: P[1] = dA, K[0] = dB, g_X*[0] = 0
// ---------------------------------------------------------------------------
__global__ void k_init(const float* __restrict__ dA, const float* __restrict__ dB) {
    int idx = blockIdx.x * 256 + threadIdx.x;
    if (idx < N_DIM * N_DIM) (&g_P[1][0][0])[idx] = dA[idx];
    if (idx < N_DIM) g_K[0][idx] = dB[idx];
    if (idx < B_DIM * N_DIM) {
        (&g_Xh[0][0][0])[idx] = __float2bfloat16(0.0f);
        (&g_Xl[0][0][0])[idx] = __float2bfloat16(0.0f);
    }
}

// ---------------------------------------------------------------------------
// power doubling: P[m+j] = P[j] @ P[m], j = 1..m
// ---------------------------------------------------------------------------
__global__ void k_power(int m) {
    int j = blockIdx.z + 1;
    const float* __restrict__ A = &g_P[j][0][0];
    const float* __restrict__ B = &g_P[m][0][0];
    float* __restrict__ C = &g_P[m + j][0][0];

    __shared__ float Ast[16][68];
    __shared__ float Bs[16][66];
    int tid = threadIdx.x, tx = tid & 15, ty = tid >> 4;
    int row0 = blockIdx.y * 64, col0 = blockIdx.x * 64;
    float2 acc[4][2] = {};

    for (int k0 = 0; k0 < N_DIM; k0 += 16) {
#pragma unroll
        for (int p = 0; p < 4; p++) {
            int idx = p * 256 + tid;
            int r = idx >> 4, kk = idx & 15;
            Ast[kk][r] = A[(row0 + r) * N_DIM + k0 + kk];
        }
#pragma unroll
        for (int p = 0; p < 4; p++) {
            int idx = p * 256 + tid;
            int kk = idx >> 6, c = idx & 63;
            Bs[kk][c] = B[(k0 + kk) * N_DIM + col0 + c];
        }
        __syncthreads();
        mm_compute(Ast, Bs, acc, ty, tx);
        __syncthreads();
    }
#pragma unroll
    for (int ii = 0; ii < 4; ii++) {
        float4 v = make_float4(acc[ii][0].x, acc[ii][0].y, acc[ii][1].x, acc[ii][1].y);
        *reinterpret_cast<float4*>(&C[(row0 + ty * 4 + ii) * N_DIM + col0 + tx * 4]) = v;
    }
}

// ---------------------------------------------------------------------------
// K[k] = P[k] @ dB, k = 1..127
// ---------------------------------------------------------------------------
__global__ void k_kvec(const float* __restrict__ dB) {
    __shared__ float sb[N_DIM];
    int k = blockIdx.x + 1;
    int i = threadIdx.x;
    sb[i] = dB[i];
    __syncthreads();
    const float4* row4 = reinterpret_cast<const float4*>(&g_P[k][i][0]);
    const float4* sb4 = reinterpret_cast<const float4*>(sb);
    float acc = 0.0f;
#pragma unroll 8
    for (int j = 0; j < N_DIM / 4; j++) {
        float4 a = row4[j], b = sb4[j];
        acc += a.x * b.x + a.y * b.y + a.z * b.z + a.w * b.w;
    }
    g_K[k][i] = acc;
}

// ---------------------------------------------------------------------------
// split into bf16 hi/lo: P[1..128], KT, reversed-padded u windows
// ---------------------------------------------------------------------------
#define R0_SPLIT (128 * 65536)
#define R1_SPLIT (256 * 128)
#define R2_SPLIT (NCHUNK * B_DIM * 256)
__global__ void k_split(const float* __restrict__ u) {
    int idx = blockIdx.x * 256 + threadIdx.x;
    if (idx < R0_SPLIT) {
        int r = 1 + (idx >> 16);
        int rem = idx & 65535;
        float x = (&g_P[r][0][0])[rem];
        __nv_bfloat16 h, l;
        split_bf16(x, h, l);
        (&g_Ph[r][0][0])[rem] = h;
        (&g_Pl[r][0][0])[rem] = l;
        return;
    }
    idx -= R0_SPLIT;
    if (idx < R1_SPLIT) {
        int i = idx >> 7, k = idx & 127;
        float x = g_K[k][i];
        __nv_bfloat16 h, l;
        split_bf16(x, h, l);
        g_KTh[i][k] = h;
        g_KTl[i][k] = l;
        return;
    }
    idx -= R1_SPLIT;
    if (idx < R2_SPLIT) {
        int c = idx >> 15;
        int b = (idx >> 8) & 127;
        int q = idx & 255;
        float x = (q <= 127) ? u[(c * CHK + 127 - q) * B_DIM + b] : 0.0f;
        __nv_bfloat16 h, l;
        split_bf16(x, h, l);
        g_uRh[c][b][q] = h;
        g_uRl[c][b][q] = l;
    }
}

// ---------------------------------------------------------------------------
// chunk-end conv (fp32): E_j[b][i] = sum_{k<128} Kvec[k][i] * u[j*128+127-k][b]
// ---------------------------------------------------------------------------
__global__ void k_etail(const float* __restrict__ u) {
    int j = blockIdx.z;
    int b0 = blockIdx.y * 64, i0 = blockIdx.x * 64;
    __shared__ float Ast[16][68];
    __shared__ float Bs[16][66];
    int tid = threadIdx.x, tx = tid & 15, ty = tid >> 4;
    float2 acc[4][2] = {};

    for (int k0 = 0; k0 < CHK; k0 += 16) {
#pragma unroll
        for (int p = 0; p < 4; p++) {
            int idx = p * 256 + tid;
            int kk = idx >> 6, bb = idx & 63;
            Ast[kk][bb] = u[(j * CHK + 127 - (k0 + kk)) * B_DIM + b0 + bb];
        }
#pragma unroll
        for (int p = 0; p < 4; p++) {
            int idx = p * 256 + tid;
            int kk = idx >> 6, ii = idx & 63;
            Bs[kk][ii] = g_K[k0 + kk][i0 + ii];
        }
        __syncthreads();
        mm_compute(Ast, Bs, acc, ty, tx);
        __syncthreads();
    }
#pragma unroll
    for (int ii = 0; ii < 4; ii++) {
        float4 v = make_float4(acc[ii][0].x, acc[ii][0].y, acc[ii][1].x, acc[ii][1].y);
        *reinterpret_cast<float4*>(&g_E[j][b0 + ty * 4 + ii][i0 + tx * 4]) = v;
    }
}

// ---------------------------------------------------------------------------
// single-launch sequential chunk scan:  X_0 = E_0 ; X_j = E_j + X_{j-1} @ P128^T
// writes bf16 splits into g_X*[j+1]. 32 CTAs x 256 threads (4 b-rows each).
// ---------------------------------------------------------------------------
__global__ void k_scanx() {
    __shared__ float s_cur[4][N_DIM];
    __shared__ float sP[N_DIM][33];
    int tid = threadIdx.x;
    int row = tid >> 6;
    int ic = tid & 63;
    int b = blockIdx.x * 4 + row;

#pragma unroll
    for (int m = 0; m < 4; m++) {
        int i = ic + m * 64;
        float v = g_E[0][b][i];
        s_cur[row][i] = v;
        __nv_bfloat16 h, l;
        split_bf16(v, h, l);
        g_Xh[1][b][i] = h;
        g_Xl[1][b][i] = l;
    }
    __syncthreads();

    for (int j = 1; j <= 14; j++) {
        float acc[4] = {0.f, 0.f, 0.f, 0.f};
        for (int k0 = 0; k0 < N_DIM; k0 += 32) {
            __syncthreads();
#pragma unroll
            for (int p = 0; p < 8; p++) {
                int e = p * 256 + tid;
                int rr = e >> 3, v = e & 7;
                float4 x = *reinterpret_cast<const float4*>(&g_P[CHK][rr][k0 + v * 4]);
                sP[rr][v * 4 + 0] = x.x;
                sP[rr][v * 4 + 1] = x.y;
                sP[rr][v * 4 + 2] = x.z;
                sP[rr][v * 4 + 3] = x.w;
            }
            __syncthreads();
#pragma unroll
            for (int kk = 0; kk < 32; kk++) {
                float xv = s_cur[row][k0 + kk];
#pragma unroll
                for (int m = 0; m < 4; m++)
                    acc[m] = fmaf(xv, sP[ic + m * 64][kk], acc[m]);
            }
        }
        __syncthreads();
#pragma unroll
        for (int m = 0; m < 4; m++) {
            int i = ic + m * 64;
            float v = g_E[j][b][i] + acc[m];
            s_cur[row][i] = v;
            __nv_bfloat16 h, l;
            split_bf16(v, h, l);
            g_Xh[j + 1][b][i] = h;
            g_Xl[j + 1][b][i] = l;
        }
        __syncthreads();
    }
}

// ---------------------------------------------------------------------------
// fused mma.sync kernel: one CTA per timestep t.
//   out[t] (128x256) = A (128x384) @ W (384x256)
//   A = [u-window(128) | X_{c-1}(256)], W = [KvecT ; P[r+1]^T]
// bf16 3-split (hh + hl + lh), fp32 accum in registers.
// 512 threads = 16 warps (4 M x 4 N), warp tile 32x64, K chunk = 64.
// smem per buffer: Ah(18432) Al(18432) Bh(36864) Bl(36864) = 110592; x2 buf.
// ---------------------------------------------------------------------------
#define BUF_BYTES 110592
#define OFF_AL 18432
#define OFF_BH 36864
#define OFF_BL 73728
#define SMEM_FUSED (2 * BUF_BYTES)

__global__ void __launch_bounds__(512, 1) k_fused(float* __restrict__ out) {
    extern __shared__ char smbuf[];
    const int tid = threadIdx.x;
    const int lane = tid & 31, wid = tid >> 5;
    const int wm = wid & 3, wn = wid >> 2;
    const int bx = blockIdx.x;
    const int r = bx >> 4;            // 16 consecutive CTAs share P[r+1]
    const int c = bx & 15;
    const int t = c * CHK + r;
    const int qoff = 127 - r;

    float acc[2][8][4];
#pragma unroll
    for (int i = 0; i < 2; i++)
#pragma unroll
        for (int j = 0; j < 8; j++)
#pragma unroll
            for (int q = 0; q < 4; q++) acc[i][j][q] = 0.f;

    // ---- staging (K chunk kc -> buffer bufsel) ----
    auto stage = [&](int kc, int bufsel) {
        char* base = smbuf + bufsel * BUF_BYTES;
        if (kc < 2) {
            __nv_bfloat16* Ah = reinterpret_cast<__nv_bfloat16*>(base);
            __nv_bfloat16* Al = reinterpret_cast<__nv_bfloat16*>(base + OFF_AL);
#pragma unroll
            for (int it = 0; it < 16; it++) {
                int e = it * 512 + tid;
                int b = e >> 6, kk = e & 63;
                int q = qoff + kc * 64 + kk;
                Ah[b * 72 + kk] = g_uRh[c][b][q];
                Al[b * 72 + kk] = g_uRl[c][b][q];
            }
#pragma unroll
            for (int it = 0; it < 4; it++) {
                int e = it * 512 + tid;
                int n = e >> 3, v = e & 7;
                *reinterpret_cast<uint4*>(base + OFF_BH + n * 144 + v * 16) =
                    *reinterpret_cast<const uint4*>(&g_KTh[n][kc * 64 + v * 8]);
                *reinterpret_cast<uint4*>(base + OFF_BL + n * 144 + v * 16) =
                    *reinterpret_cast<const uint4*>(&g_KTl[n][kc * 64 + v * 8]);
            }
        } else {
            int kb = (kc - 2) * 64;
#pragma unroll
            for (int it = 0; it < 2; it++) {
                int e = it * 512 + tid;
                int b = e >> 3, v = e & 7;
                *reinterpret_cast<uint4*>(base + b * 144 + v * 16) =
                    *reinterpret_cast<const uint4*>(&g_Xh[c][b][kb + v * 8]);
                *reinterpret_cast<uint4*>(base + OFF_AL + b * 144 + v * 16) =
                    *reinterpret_cast<const uint4*>(&g_Xl[c][b][kb + v * 8]);
            }
#pragma unroll
            for (int it = 0; it < 4; it++) {
                int e = it * 512 + tid;
                int n = e >> 3, v = e & 7;
                *reinterpret_cast<uint4*>(base + OFF_BH + n * 144 + v * 16) =
                    *reinterpret_cast<const uint4*>(&g_Ph[r + 1][n][kb + v * 8]);
                *reinterpret_cast<uint4*>(base + OFF_BL + n * 144 + v * 16) =
                    *reinterpret_cast<const uint4*>(&g_Pl[r + 1][n][kb + v * 8]);
            }
        }
    };

    // per-thread fragment base byte offsets (within A / B tiles)
    const int aoffT = (wm * 32 + (lane >> 2)) * 144 + (lane & 3) * 4;
    const int boffT = (wn * 64 + (lane >> 2)) * 144 + (lane & 3) * 4;

    auto product = [&](const char* Abase, const char* Bbase) {
#pragma unroll
        for (int ks = 0; ks < 4; ks++) {
            uint32_t af[2][4];
#pragma unroll
            for (int ma = 0; ma < 2; ma++) {
                const char* p = Abase + aoffT + ma * (16 * 144) + ks * 32;
                af[ma][0] = *reinterpret_cast<const uint32_t*>(p);
                af[ma][1] = *reinterpret_cast<const uint32_t*>(p + 8 * 144);
                af[ma][2] = *reinterpret_cast<const uint32_t*>(p + 16);
                af[ma][3] = *reinterpret_cast<const uint32_t*>(p + 8 * 144 + 16);
            }
#pragma unroll
            for (int nb = 0; nb < 8; nb++) {
                const char* p = Bbase + boffT + nb * (8 * 144) + ks * 32;
                uint32_t b0 = *reinterpret_cast<const uint32_t*>(p);
                uint32_t b1 = *reinterpret_cast<const uint32_t*>(p + 16);
                mma_bf16(acc[0][nb], af[0], b0, b1);
                mma_bf16(acc[1][nb], af[1], b0, b1);
            }
        }
    };

    stage(0, 0);
    __syncthreads();
#pragma unroll 1
    for (int kc = 0; kc < 6; kc++) {
        if (kc + 1 < 6) stage(kc + 1, (kc + 1) & 1);
        const char* buf = smbuf + (kc & 1) * BUF_BYTES;
        product(buf, buf + OFF_BH);            // Ah * Bh
        product(buf, buf + OFF_BL);            // Ah * Bl
        product(buf + OFF_AL, buf + OFF_BH);   // Al * Bh
        __syncthreads();
    }

    // epilogue: direct fp32 stores (streaming, write-once)
    float* outt = out + (size_t)t * B_DIM * N_DIM;
#pragma unroll
    for (int ma = 0; ma < 2; ma++) {
        int row = wm * 32 + ma * 16 + (lane >> 2);
#pragma unroll
        for (int nb = 0; nb < 8; nb++) {
            int col = wn * 64 + nb * 8 + (lane & 3) * 2;
            *reinterpret_cast<float2*>(outt + row * 256 + col) =
                make_float2(acc[ma][nb][0], acc[ma][nb][1]);
            *reinterpret_cast<float2*>(outt + (row + 8) * 256 + col) =
                make_float2(acc[ma][nb][2], acc[ma][nb][3]);
        }
    }
}

// ---------------------------------------------------------------------------
extern "C" void kernel_launch(void* const* d_in, const int* in_sizes, int n_in,
                              void* d_out, int out_size) {
    const float* u  = (const float*)d_in[0];   // [L, B]
    const float* dA = (const float*)d_in[1];   // [N, N]
    const float* dB = (const float*)d_in[2];   // [N]
    float* out = (float*)d_out;                // [L, B, N]

    cudaFuncSetAttribute(k_fused, cudaFuncAttributeMaxDynamicSharedMemorySize, SMEM_FUSED);

    k_init<<<256, 256>>>(dA, dB);
    for (int m = 1; m < CHK; m <<= 1)
        k_power<<<dim3(4, 4, m), 256>>>(m);
    k_kvec<<<CHK - 1, 256>>>(dB);
    {
        int total = R0_SPLIT + R1_SPLIT + R2_SPLIT;
        k_split<<<(total + 255) / 256, 256>>>(u);
    }
    k_etail<<<dim3(4, 2, NCHUNK), 256>>>(u);
    k_scanx<<<32, 256>>>();
    k_fused<<<L_DIM, 512, SMEM_FUSED>>>(out);
}

// round 4
// speedup vs baseline: 2.3135x; 1.0754x over previous
#include <cuda_runtime.h>
#include <cuda_bf16.h>
#include <cstdint>

// Problem constants
#define N_DIM 256
#define L_DIM 2048
#define B_DIM 128
#define CHK   128
#define NCHUNK 16

// ---------------------------------------------------------------------------
// Device global scratch (allocation-free rules)
// ---------------------------------------------------------------------------
__device__ float g_P[CHK + 1][N_DIM][N_DIM];        // dA^p, p = 1..128
__device__ float g_K[CHK][N_DIM];                   // Kvec[k] = dA^k dB
__device__ float g_E[NCHUNK][B_DIM][N_DIM];         // chunk-end conv values
__device__ __nv_bfloat16 g_Ph[CHK + 1][N_DIM][N_DIM];
__device__ __nv_bfloat16 g_Pl[CHK + 1][N_DIM][N_DIM];
__device__ __nv_bfloat16 g_KTh[N_DIM][CHK];
__device__ __nv_bfloat16 g_KTl[N_DIM][CHK];
__device__ __nv_bfloat16 g_uRh[NCHUNK][B_DIM][256]; // reversed padded u windows
__device__ __nv_bfloat16 g_uRl[NCHUNK][B_DIM][256];
__device__ __nv_bfloat16 g_Xh[NCHUNK][B_DIM][N_DIM]; // g_X*[c] = X_{c-1}; [0]=0
__device__ __nv_bfloat16 g_Xl[NCHUNK][B_DIM][N_DIM];

// ---------------------------------------------------------------------------
// helpers
// ---------------------------------------------------------------------------
__device__ __forceinline__ void ffma2(float2& c, float2 a, float2 b) {
    asm("{\n\t"
        ".reg .b64 ra, rb, rc;\n\t"
        "mov.b64 ra, {%2, %3};\n\t"
        "mov.b64 rb, {%4, %5};\n\t"
        "mov.b64 rc, {%0, %1};\n\t"
        "fma.rn.f32x2 rc, ra, rb, rc;\n\t"
        "mov.b64 {%0, %1}, rc;\n\t"
        "}"
        : "+f"(c.x), "+f"(c.y)
        : "f"(a.x), "f"(a.y), "f"(b.x), "f"(b.y));
}

__device__ __forceinline__ void split_bf16(float x, __nv_bfloat16& h, __nv_bfloat16& l) {
    h = __float2bfloat16(x);
    l = __float2bfloat16(x - __bfloat162float(h));
}

__device__ __forceinline__ uint32_t smem_u32(const void* p) {
    uint32_t a;
    asm("{ .reg .u64 t; cvta.to.shared.u64 t, %1; cvt.u32.u64 %0, t; }" : "=r"(a) : "l"(p));
    return a;
}

__device__ __forceinline__ void mma_bf16(float d[4], const uint32_t a[4],
                                         uint32_t b0, uint32_t b1) {
    asm volatile(
        "mma.sync.aligned.m16n8k16.row.col.f32.bf16.bf16.f32 "
        "{%0,%1,%2,%3}, {%4,%5,%6,%7}, {%8,%9}, {%0,%1,%2,%3};"
        : "+f"(d[0]), "+f"(d[1]), "+f"(d[2]), "+f"(d[3])
        : "r"(a[0]), "r"(a[1]), "r"(a[2]), "r"(a[3]), "r"(b0), "r"(b1));
}

__device__ __forceinline__ void ldsm4(uint32_t* r, uint32_t addr) {
    asm volatile("ldmatrix.sync.aligned.m8n8.x4.shared.b16 {%0,%1,%2,%3}, [%4];"
                 : "=r"(r[0]), "=r"(r[1]), "=r"(r[2]), "=r"(r[3]) : "r"(addr));
}

__device__ __forceinline__ void cp16(uint32_t sdst, const void* gsrc) {
    asm volatile("cp.async.cg.shared.global [%0], [%1], 16;" :: "r"(sdst), "l"(gsrc));
}
__device__ __forceinline__ void cp_commit() {
    asm volatile("cp.async.commit_group;" ::: "memory");
}
template <int NW>
__device__ __forceinline__ void cp_wait() {
    asm volatile("cp.async.wait_group %0;" :: "n"(NW) : "memory");
}

// ---------------------------------------------------------------------------
// fp32 64x64 micro-kernel (setup GEMMs)
// ---------------------------------------------------------------------------
__device__ __forceinline__ void mm_compute(const float (*Ast)[68], const float (*Bs)[66],
                                           float2 acc[4][2], int ty, int tx) {
#pragma unroll
    for (int kk = 0; kk < 16; kk++) {
        float2 b0 = *reinterpret_cast<const float2*>(&Bs[kk][tx * 4]);
        float2 b1 = *reinterpret_cast<const float2*>(&Bs[kk][tx * 4 + 2]);
#pragma unroll
        for (int ii = 0; ii < 4; ii++) {
            float a = Ast[kk][ty * 4 + ii];
            float2 a2 = make_float2(a, a);
            ffma2(acc[ii][0], a2, b0);
            ffma2(acc[ii][1], a2, b1);
        }
    }
}

// ---------------------------------------------------------------------------
// init: P[1] = dA (+ splits), K[0] = dB, g_X*[0] = 0
// ---------------------------------------------------------------------------
__global__ void k_init(const float* __restrict__ dA, const float* __restrict__ dB) {
    int idx = blockIdx.x * 256 + threadIdx.x;
    if (idx < N_DIM * N_DIM) {
        float x = dA[idx];
        (&g_P[1][0][0])[idx] = x;
        __nv_bfloat16 h, l;
        split_bf16(x, h, l);
        (&g_Ph[1][0][0])[idx] = h;
        (&g_Pl[1][0][0])[idx] = l;
    }
    if (idx < N_DIM) g_K[0][idx] = dB[idx];
    if (idx < B_DIM * N_DIM) {
        (&g_Xh[0][0][0])[idx] = __float2bfloat16(0.0f);
        (&g_Xl[0][0][0])[idx] = __float2bfloat16(0.0f);
    }
}

// ---------------------------------------------------------------------------
// power doubling: P[m+j] = P[j] @ P[m], j = 1..m  (double-buffered)
// epilogue also writes bf16 hi/lo splits.
// ---------------------------------------------------------------------------
__global__ void k_power(int m) {
    int j = blockIdx.z + 1;
    const float* __restrict__ A = &g_P[j][0][0];
    const float* __restrict__ B = &g_P[m][0][0];
    float* __restrict__ C = &g_P[m + j][0][0];
    __nv_bfloat16* __restrict__ Ch = &g_Ph[m + j][0][0];
    __nv_bfloat16* __restrict__ Cl = &g_Pl[m + j][0][0];

    __shared__ float Ast[2][16][68];
    __shared__ float Bs[2][16][66];
    int tid = threadIdx.x, tx = tid & 15, ty = tid >> 4;
    int row0 = blockIdx.y * 64, col0 = blockIdx.x * 64;
    float2 acc[4][2] = {};
    float ra[4], rb[4];

    auto g2r = [&](int k0) {
#pragma unroll
        for (int p = 0; p < 4; p++) {
            int idx = p * 256 + tid;
            ra[p] = A[(row0 + (idx >> 4)) * N_DIM + k0 + (idx & 15)];
        }
#pragma unroll
        for (int p = 0; p < 4; p++) {
            int idx = p * 256 + tid;
            rb[p] = B[(k0 + (idx >> 6)) * N_DIM + col0 + (idx & 63)];
        }
    };
    auto r2s = [&](int bsel) {
#pragma unroll
        for (int p = 0; p < 4; p++) {
            int idx = p * 256 + tid;
            Ast[bsel][idx & 15][idx >> 4] = ra[p];
        }
#pragma unroll
        for (int p = 0; p < 4; p++) {
            int idx = p * 256 + tid;
            Bs[bsel][idx >> 6][idx & 63] = rb[p];
        }
    };

    g2r(0);
    r2s(0);
    __syncthreads();
#pragma unroll 1
    for (int kc = 0; kc < 16; kc++) {
        if (kc + 1 < 16) g2r((kc + 1) * 16);
        mm_compute(Ast[kc & 1], Bs[kc & 1], acc, ty, tx);
        __syncthreads();
        if (kc + 1 < 16) {
            r2s((kc + 1) & 1);
            __syncthreads();
        }
    }
#pragma unroll
    for (int ii = 0; ii < 4; ii++) {
        int row = row0 + ty * 4 + ii, col = col0 + tx * 4;
        float4 v = make_float4(acc[ii][0].x, acc[ii][0].y, acc[ii][1].x, acc[ii][1].y);
        *reinterpret_cast<float4*>(&C[row * N_DIM + col]) = v;
        __nv_bfloat16 h, l;
        split_bf16(v.x, h, l); Ch[row * N_DIM + col + 0] = h; Cl[row * N_DIM + col + 0] = l;
        split_bf16(v.y, h, l); Ch[row * N_DIM + col + 1] = h; Cl[row * N_DIM + col + 1] = l;
        split_bf16(v.z, h, l); Ch[row * N_DIM + col + 2] = h; Cl[row * N_DIM + col + 2] = l;
        split_bf16(v.w, h, l); Ch[row * N_DIM + col + 3] = h; Cl[row * N_DIM + col + 3] = l;
    }
}

// ---------------------------------------------------------------------------
// K[k] = P[k] @ dB, k = 1..127
// ---------------------------------------------------------------------------
__global__ void k_kvec(const float* __restrict__ dB) {
    __shared__ float sb[N_DIM];
    int k = blockIdx.x + 1;
    int i = threadIdx.x;
    sb[i] = dB[i];
    __syncthreads();
    const float4* row4 = reinterpret_cast<const float4*>(&g_P[k][i][0]);
    const float4* sb4 = reinterpret_cast<const float4*>(sb);
    float acc = 0.0f;
#pragma unroll 8
    for (int j = 0; j < N_DIM / 4; j++) {
        float4 a = row4[j], b = sb4[j];
        acc += a.x * b.x + a.y * b.y + a.z * b.z + a.w * b.w;
    }
    g_K[k][i] = acc;
}

// ---------------------------------------------------------------------------
// split KT + reversed-padded u windows into bf16 hi/lo
// ---------------------------------------------------------------------------
#define R1_SPLIT (256 * 128)
#define R2_SPLIT (NCHUNK * B_DIM * 256)
__global__ void k_split(const float* __restrict__ u) {
    int idx = blockIdx.x * 256 + threadIdx.x;
    if (idx < R1_SPLIT) {
        int i = idx >> 7, k = idx & 127;
        float x = g_K[k][i];
        __nv_bfloat16 h, l;
        split_bf16(x, h, l);
        g_KTh[i][k] = h;
        g_KTl[i][k] = l;
        return;
    }
    idx -= R1_SPLIT;
    if (idx < R2_SPLIT) {
        int c = idx >> 15;
        int b = (idx >> 8) & 127;
        int q = idx & 255;
        float x = (q <= 127) ? u[(c * CHK + 127 - q) * B_DIM + b] : 0.0f;
        __nv_bfloat16 h, l;
        split_bf16(x, h, l);
        g_uRh[c][b][q] = h;
        g_uRl[c][b][q] = l;
    }
}

// ---------------------------------------------------------------------------
// chunk-end conv (fp32): E_j[b][i] = sum_{k<128} Kvec[k][i] * u[j*128+127-k][b]
// ---------------------------------------------------------------------------
__global__ void k_etail(const float* __restrict__ u) {
    int j = blockIdx.z;
    int b0 = blockIdx.y * 64, i0 = blockIdx.x * 64;
    __shared__ float Ast[16][68];
    __shared__ float Bs[16][66];
    int tid = threadIdx.x, tx = tid & 15, ty = tid >> 4;
    float2 acc[4][2] = {};

    for (int k0 = 0; k0 < CHK; k0 += 16) {
#pragma unroll
        for (int p = 0; p < 4; p++) {
            int idx = p * 256 + tid;
            int kk = idx >> 6, bb = idx & 63;
            Ast[kk][bb] = u[(j * CHK + 127 - (k0 + kk)) * B_DIM + b0 + bb];
        }
#pragma unroll
        for (int p = 0; p < 4; p++) {
            int idx = p * 256 + tid;
            int kk = idx >> 6, ii = idx & 63;
            Bs[kk][ii] = g_K[k0 + kk][i0 + ii];
        }
        __syncthreads();
        mm_compute(Ast, Bs, acc, ty, tx);
        __syncthreads();
    }
#pragma unroll
    for (int ii = 0; ii < 4; ii++) {
        float4 v = make_float4(acc[ii][0].x, acc[ii][0].y, acc[ii][1].x, acc[ii][1].y);
        *reinterpret_cast<float4*>(&g_E[j][b0 + ty * 4 + ii][i0 + tx * 4]) = v;
    }
}

// ---------------------------------------------------------------------------
// single-launch sequential chunk scan:  X_0 = E_0 ; X_j = E_j + X_{j-1} @ P128^T
// ---------------------------------------------------------------------------
__global__ void k_scanx() {
    __shared__ float s_cur[4][N_DIM];
    __shared__ float sP[N_DIM][33];
    int tid = threadIdx.x;
    int row = tid >> 6;
    int ic = tid & 63;
    int b = blockIdx.x * 4 + row;

#pragma unroll
    for (int m = 0; m < 4; m++) {
        int i = ic + m * 64;
        float v = g_E[0][b][i];
        s_cur[row][i] = v;
        __nv_bfloat16 h, l;
        split_bf16(v, h, l);
        g_Xh[1][b][i] = h;
        g_Xl[1][b][i] = l;
    }
    __syncthreads();

    for (int j = 1; j <= 14; j++) {
        float acc[4] = {0.f, 0.f, 0.f, 0.f};
        for (int k0 = 0; k0 < N_DIM; k0 += 32) {
            __syncthreads();
#pragma unroll
            for (int p = 0; p < 8; p++) {
                int e = p * 256 + tid;
                int rr = e >> 3, v = e & 7;
                float4 x = *reinterpret_cast<const float4*>(&g_P[CHK][rr][k0 + v * 4]);
                sP[rr][v * 4 + 0] = x.x;
                sP[rr][v * 4 + 1] = x.y;
                sP[rr][v * 4 + 2] = x.z;
                sP[rr][v * 4 + 3] = x.w;
            }
            __syncthreads();
#pragma unroll
            for (int kk = 0; kk < 32; kk++) {
                float xv = s_cur[row][k0 + kk];
#pragma unroll
                for (int m = 0; m < 4; m++)
                    acc[m] = fmaf(xv, sP[ic + m * 64][kk], acc[m]);
            }
        }
        __syncthreads();
#pragma unroll
        for (int m = 0; m < 4; m++) {
            int i = ic + m * 64;
            float v = g_E[j][b][i] + acc[m];
            s_cur[row][i] = v;
            __nv_bfloat16 h, l;
            split_bf16(v, h, l);
            g_Xh[j + 1][b][i] = h;
            g_Xl[j + 1][b][i] = l;
        }
        __syncthreads();
    }
}

// ---------------------------------------------------------------------------
// fused mma kernel, rewritten: 256 threads = 8 warps (2 wm x 4 wn),
// warp tile M64 x N64, ldmatrix fragment loads shared across 3 products,
// cp.async double-buffered staging.
//   out[t](128x256) = [uR | X] (128x384) @ [KT ; P[r+1]] (as [n][k])
// ---------------------------------------------------------------------------
#define FSTRIDE 144
#define F_OFF_AL 18432
#define F_OFF_BH 36864
#define F_OFF_BL 73728
#define F_BUF    110592
#define SMEM_FUSED (2 * F_BUF)

__global__ void __launch_bounds__(256, 1) k_fused(float* __restrict__ out) {
    extern __shared__ char smbuf[];
    const uint32_t sb = smem_u32(smbuf);
    const int tid = threadIdx.x;
    const int lane = tid & 31, wid = tid >> 5;
    const int wm = wid & 1, wn = wid >> 1;      // 2 x 4 warp grid
    const int bx = blockIdx.x;
    const int r = bx >> 4, c = bx & 15;         // 16 consecutive CTAs share P[r+1]
    const int t = c * CHK + r;
    const int qoff = 127 - r;

    float acc[4][8][4];
#pragma unroll
    for (int ma = 0; ma < 4; ma++)
#pragma unroll
        for (int nb = 0; nb < 8; nb++)
#pragma unroll
            for (int q = 0; q < 4; q++) acc[ma][nb][q] = 0.f;

    auto stage = [&](int kc, int bufsel) {
        uint32_t base = sb + bufsel * F_BUF;
        char* cbase = smbuf + bufsel * F_BUF;
        if (kc < 2) {
            // B <- KT rows (cp.async)
#pragma unroll
            for (int it = 0; it < 8; it++) {
                int e = it * 256 + tid;
                int n = e >> 3, v = e & 7;
                cp16(base + F_OFF_BH + n * FSTRIDE + v * 16, &g_KTh[n][kc * 64 + v * 8]);
                cp16(base + F_OFF_BL + n * FSTRIDE + v * 16, &g_KTl[n][kc * 64 + v * 8]);
            }
            // A <- u window (synchronous; unaligned shift)
            int q0 = qoff + kc * 64;
            if ((q0 & 1) == 0) {
#pragma unroll
                for (int it = 0; it < 16; it++) {
                    int e = it * 256 + tid;
                    int b = e >> 5, jp = e & 31;
                    uint32_t hv = *reinterpret_cast<const uint32_t*>(&g_uRh[c][b][q0 + jp * 2]);
                    uint32_t lv = *reinterpret_cast<const uint32_t*>(&g_uRl[c][b][q0 + jp * 2]);
                    *reinterpret_cast<uint32_t*>(cbase + b * FSTRIDE + jp * 4) = hv;
                    *reinterpret_cast<uint32_t*>(cbase + F_OFF_AL + b * FSTRIDE + jp * 4) = lv;
                }
            } else {
#pragma unroll
                for (int it = 0; it < 16; it++) {
                    int e = it * 256 + tid;
                    int b = e >> 5, jp = e & 31;
                    __nv_bfloat162 hv = make_bfloat162(g_uRh[c][b][q0 + jp * 2],
                                                       g_uRh[c][b][q0 + jp * 2 + 1]);
                    __nv_bfloat162 lv = make_bfloat162(g_uRl[c][b][q0 + jp * 2],
                                                       g_uRl[c][b][q0 + jp * 2 + 1]);
                    *reinterpret_cast<__nv_bfloat162*>(cbase + b * FSTRIDE + jp * 4) = hv;
                    *reinterpret_cast<__nv_bfloat162*>(cbase + F_OFF_AL + b * FSTRIDE + jp * 4) = lv;
                }
            }
        } else {
            int kb = (kc - 2) * 64;
            // A <- X splits
#pragma unroll
            for (int it = 0; it < 4; it++) {
                int e = it * 256 + tid;
                int b = e >> 3, v = e & 7;
                cp16(base + b * FSTRIDE + v * 16, &g_Xh[c][b][kb + v * 8]);
                cp16(base + F_OFF_AL + b * FSTRIDE + v * 16, &g_Xl[c][b][kb + v * 8]);
            }
            // B <- P[r+1] splits
#pragma unroll
            for (int it = 0; it < 8; it++) {
                int e = it * 256 + tid;
                int n = e >> 3, v = e & 7;
                cp16(base + F_OFF_BH + n * FSTRIDE + v * 16, &g_Ph[r + 1][n][kb + v * 8]);
                cp16(base + F_OFF_BL + n * FSTRIDE + v * 16, &g_Pl[r + 1][n][kb + v * 8]);
            }
        }
    };

    auto compute = [&](int bufsel) {
        uint32_t base = sb + bufsel * F_BUF;
        uint32_t aA = base + (wm * 64 + (lane & 15)) * FSTRIDE + (lane >> 4) * 16;
        uint32_t aB = base + F_OFF_BH + (wn * 64 + (lane & 15)) * FSTRIDE + (lane >> 4) * 16;
#pragma unroll
        for (int ks = 0; ks < 4; ks++) {
            uint32_t Ah[16], Al[16];
#pragma unroll
            for (int ma = 0; ma < 4; ma++) {
                ldsm4(&Ah[ma * 4], aA + ma * (16 * FSTRIDE) + ks * 32);
                ldsm4(&Al[ma * 4], aA + F_OFF_AL + ma * (16 * FSTRIDE) + ks * 32);
            }
#pragma unroll
            for (int pr = 0; pr < 4; pr++) {
                uint32_t bh[4], bl[4];
                ldsm4(bh, aB + pr * (16 * FSTRIDE) + ks * 32);
                ldsm4(bl, aB + (F_OFF_BL - F_OFF_BH) + pr * (16 * FSTRIDE) + ks * 32);
#pragma unroll
                for (int sub = 0; sub < 2; sub++) {
                    int nb = pr * 2 + sub;
                    uint32_t b0h = bh[sub], b1h = bh[2 + sub];
                    uint32_t b0l = bl[sub], b1l = bl[2 + sub];
#pragma unroll
                    for (int ma = 0; ma < 4; ma++) {
                        mma_bf16(acc[ma][nb], &Ah[ma * 4], b0h, b1h);
                        mma_bf16(acc[ma][nb], &Ah[ma * 4], b0l, b1l);
                        mma_bf16(acc[ma][nb], &Al[ma * 4], b0h, b1h);
                    }
                }
            }
        }
    };

    stage(0, 0);
    cp_commit();
#pragma unroll 1
    for (int kc = 0; kc < 6; kc++) {
        if (kc < 5) {
            stage(kc + 1, (kc + 1) & 1);
            cp_commit();
        }
        if (kc < 5) cp_wait<1>(); else cp_wait<0>();
        __syncthreads();
        compute(kc & 1);
        __syncthreads();
    }

    // epilogue: direct fp32 stores
    float* outt = out + (size_t)t * (B_DIM * N_DIM);
#pragma unroll
    for (int ma = 0; ma < 4; ma++) {
        int row = wm * 64 + ma * 16 + (lane >> 2);
#pragma unroll
        for (int nb = 0; nb < 8; nb++) {
            int col = wn * 64 + nb * 8 + (lane & 3) * 2;
            *reinterpret_cast<float2*>(outt + row * 256 + col) =
                make_float2(acc[ma][nb][0], acc[ma][nb][1]);
            *reinterpret_cast<float2*>(outt + (row + 8) * 256 + col) =
                make_float2(acc[ma][nb][2], acc[ma][nb][3]);
        }
    }
}

// ---------------------------------------------------------------------------
extern "C" void kernel_launch(void* const* d_in, const int* in_sizes, int n_in,
                              void* d_out, int out_size) {
    const float* u  = (const float*)d_in[0];   // [L, B]
    const float* dA = (const float*)d_in[1];   // [N, N]
    const float* dB = (const float*)d_in[2];   // [N]
    float* out = (float*)d_out;                // [L, B, N]

    cudaFuncSetAttribute(k_fused, cudaFuncAttributeMaxDynamicSharedMemorySize, SMEM_FUSED);

    k_init<<<256, 256>>>(dA, dB);
    for (int m = 1; m < CHK; m <<= 1)
        k_power<<<dim3(4, 4, m), 256>>>(m);
    k_kvec<<<CHK - 1, 256>>>(dB);
    {
        int total = R1_SPLIT + R2_SPLIT;
        k_split<<<(total + 255) / 256, 256>>>(u);
    }
    k_etail<<<dim3(4, 2, NCHUNK), 256>>>(u);
    k_scanx<<<32, 256>>>();
    k_fused<<<L_DIM, 256, SMEM_FUSED>>>(out);
}

// round 5
// speedup vs baseline: 2.7367x; 1.1829x over previous
#include <cuda_runtime.h>
#include <cuda_bf16.h>
#include <cstdint>

// Problem constants
#define N_DIM 256
#define L_DIM 2048
#define B_DIM 128
#define CHK   128
#define NCHUNK 16

// ---------------------------------------------------------------------------
// Device global scratch (allocation-free rules)
// ---------------------------------------------------------------------------
__device__ float g_P[CHK + 1][N_DIM][N_DIM];        // dA^p, p = 1..128
__device__ float g_K[CHK][N_DIM];                   // Kvec[k] = dA^k dB
__device__ float g_E[NCHUNK][B_DIM][N_DIM];         // chunk-end conv values
__device__ __nv_bfloat16 g_Ph[CHK + 1][N_DIM][N_DIM];
__device__ __nv_bfloat16 g_Pl[CHK + 1][N_DIM][N_DIM];
__device__ __nv_bfloat16 g_KTh[N_DIM][CHK];
__device__ __nv_bfloat16 g_KTl[N_DIM][CHK];
__device__ __nv_bfloat16 g_uRh[NCHUNK][B_DIM][256]; // reversed padded u windows
__device__ __nv_bfloat16 g_uRl[NCHUNK][B_DIM][256];
__device__ __nv_bfloat16 g_Xh[NCHUNK][B_DIM][N_DIM]; // g_X*[c] = X_{c-1}; [0]=0
__device__ __nv_bfloat16 g_Xl[NCHUNK][B_DIM][N_DIM];

// ---------------------------------------------------------------------------
// helpers
// ---------------------------------------------------------------------------
__device__ __forceinline__ void ffma2(float2& c, float2 a, float2 b) {
    asm("{\n\t"
        ".reg .b64 ra, rb, rc;\n\t"
        "mov.b64 ra, {%2, %3};\n\t"
        "mov.b64 rb, {%4, %5};\n\t"
        "mov.b64 rc, {%0, %1};\n\t"
        "fma.rn.f32x2 rc, ra, rb, rc;\n\t"
        "mov.b64 {%0, %1}, rc;\n\t"
        "}"
        : "+f"(c.x), "+f"(c.y)
        : "f"(a.x), "f"(a.y), "f"(b.x), "f"(b.y));
}

__device__ __forceinline__ void split_bf16(float x, __nv_bfloat16& h, __nv_bfloat16& l) {
    h = __float2bfloat16(x);
    l = __float2bfloat16(x - __bfloat162float(h));
}

__device__ __forceinline__ uint32_t smem_u32(const void* p) {
    uint32_t a;
    asm("{ .reg .u64 t; cvta.to.shared.u64 t, %1; cvt.u32.u64 %0, t; }" : "=r"(a) : "l"(p));
    return a;
}

__device__ __forceinline__ void mma_bf16(float d[4], const uint32_t a[4],
                                         uint32_t b0, uint32_t b1) {
    asm volatile(
        "mma.sync.aligned.m16n8k16.row.col.f32.bf16.bf16.f32 "
        "{%0,%1,%2,%3}, {%4,%5,%6,%7}, {%8,%9}, {%0,%1,%2,%3};"
        : "+f"(d[0]), "+f"(d[1]), "+f"(d[2]), "+f"(d[3])
        : "r"(a[0]), "r"(a[1]), "r"(a[2]), "r"(a[3]), "r"(b0), "r"(b1));
}

__device__ __forceinline__ void ldsm4(uint32_t* r, uint32_t addr) {
    asm volatile("ldmatrix.sync.aligned.m8n8.x4.shared.b16 {%0,%1,%2,%3}, [%4];"
                 : "=r"(r[0]), "=r"(r[1]), "=r"(r[2]), "=r"(r[3]) : "r"(addr));
}

__device__ __forceinline__ void cp16(uint32_t sdst, const void* gsrc) {
    asm volatile("cp.async.cg.shared.global [%0], [%1], 16;" :: "r"(sdst), "l"(gsrc));
}
__device__ __forceinline__ void cp_commit() {
    asm volatile("cp.async.commit_group;" ::: "memory");
}
template <int NW>
__device__ __forceinline__ void cp_wait() {
    asm volatile("cp.async.wait_group %0;" :: "n"(NW) : "memory");
}

// ---------------------------------------------------------------------------
// init: P[1] = dA (+ splits), K[0] = dB, g_X*[0] = 0
// ---------------------------------------------------------------------------
__global__ void k_init(const float* __restrict__ dA, const float* __restrict__ dB) {
    int idx = blockIdx.x * 256 + threadIdx.x;
    if (idx < N_DIM * N_DIM) {
        float x = dA[idx];
        (&g_P[1][0][0])[idx] = x;
        __nv_bfloat16 h, l;
        split_bf16(x, h, l);
        (&g_Ph[1][0][0])[idx] = h;
        (&g_Pl[1][0][0])[idx] = l;
    }
    if (idx < N_DIM) g_K[0][idx] = dB[idx];
    if (idx < B_DIM * N_DIM) {
        (&g_Xh[0][0][0])[idx] = __float2bfloat16(0.0f);
        (&g_Xl[0][0][0])[idx] = __float2bfloat16(0.0f);
    }
}

// ---------------------------------------------------------------------------
// power doubling: P[m+j] = P[j] @ P[m], j = 1..m
// 4-stage cp.async pipeline, K-slice 16. Epilogue writes bf16 splits too.
// ---------------------------------------------------------------------------
__global__ void k_power(int m) {
    int j = blockIdx.z + 1;
    const float* __restrict__ A = &g_P[j][0][0];
    const float* __restrict__ B = &g_P[m][0][0];
    float* __restrict__ C = &g_P[m + j][0][0];
    __nv_bfloat16* __restrict__ Ch = &g_Ph[m + j][0][0];
    __nv_bfloat16* __restrict__ Cl = &g_Pl[m + j][0][0];

    __shared__ __align__(16) float As[4][64][20];   // [stage][row][k(16)+pad]
    __shared__ __align__(16) float Bs[4][16][68];   // [stage][k][col(64)+pad]
    int tid = threadIdx.x, tx = tid & 15, ty = tid >> 4;
    int row0 = blockIdx.y * 64, col0 = blockIdx.x * 64;

    auto issue = [&](int kc) {
        int s = kc & 3;
        int k0 = kc * 16;
        {
            int row = tid >> 2, v = tid & 3;
            cp16(smem_u32(&As[s][row][v * 4]), &A[(row0 + row) * N_DIM + k0 + v * 4]);
        }
        {
            int row = tid >> 4, v = tid & 15;
            cp16(smem_u32(&Bs[s][row][v * 4]), &B[(k0 + row) * N_DIM + col0 + v * 4]);
        }
        cp_commit();
    };

    issue(0); issue(1); issue(2);

    float2 acc[4][2] = {};
#pragma unroll 1
    for (int kc = 0; kc < 16; kc++) {
        if (kc <= 13) cp_wait<2>();
        else if (kc == 14) cp_wait<1>();
        else cp_wait<0>();
        __syncthreads();
        if (kc + 3 < 16) issue(kc + 3);
        int s = kc & 3;
#pragma unroll
        for (int kk4 = 0; kk4 < 4; kk4++) {
            float4 a4[4];
#pragma unroll
            for (int ii = 0; ii < 4; ii++)
                a4[ii] = *reinterpret_cast<const float4*>(&As[s][ty * 4 + ii][kk4 * 4]);
#pragma unroll
            for (int q = 0; q < 4; q++) {
                int kk = kk4 * 4 + q;
                float2 b0 = *reinterpret_cast<const float2*>(&Bs[s][kk][tx * 4]);
                float2 b1 = *reinterpret_cast<const float2*>(&Bs[s][kk][tx * 4 + 2]);
#pragma unroll
                for (int ii = 0; ii < 4; ii++) {
                    float av = (q == 0) ? a4[ii].x : (q == 1) ? a4[ii].y
                             : (q == 2) ? a4[ii].z : a4[ii].w;
                    float2 a2 = make_float2(av, av);
                    ffma2(acc[ii][0], a2, b0);
                    ffma2(acc[ii][1], a2, b1);
                }
            }
        }
    }
#pragma unroll
    for (int ii = 0; ii < 4; ii++) {
        int row = row0 + ty * 4 + ii, col = col0 + tx * 4;
        float4 v = make_float4(acc[ii][0].x, acc[ii][0].y, acc[ii][1].x, acc[ii][1].y);
        *reinterpret_cast<float4*>(&C[row * N_DIM + col]) = v;
        __nv_bfloat16 h, l;
        split_bf16(v.x, h, l); Ch[row * N_DIM + col + 0] = h; Cl[row * N_DIM + col + 0] = l;
        split_bf16(v.y, h, l); Ch[row * N_DIM + col + 1] = h; Cl[row * N_DIM + col + 1] = l;
        split_bf16(v.z, h, l); Ch[row * N_DIM + col + 2] = h; Cl[row * N_DIM + col + 2] = l;
        split_bf16(v.w, h, l); Ch[row * N_DIM + col + 3] = h; Cl[row * N_DIM + col + 3] = l;
    }
}

// ---------------------------------------------------------------------------
// K[k] = P[k] @ dB, k = 1..127
// ---------------------------------------------------------------------------
__global__ void k_kvec(const float* __restrict__ dB) {
    __shared__ float sb[N_DIM];
    int k = blockIdx.x + 1;
    int i = threadIdx.x;
    sb[i] = dB[i];
    __syncthreads();
    const float4* row4 = reinterpret_cast<const float4*>(&g_P[k][i][0]);
    const float4* sb4 = reinterpret_cast<const float4*>(sb);
    float acc = 0.0f;
#pragma unroll 8
    for (int j = 0; j < N_DIM / 4; j++) {
        float4 a = row4[j], b = sb4[j];
        acc += a.x * b.x + a.y * b.y + a.z * b.z + a.w * b.w;
    }
    g_K[k][i] = acc;
}

// ---------------------------------------------------------------------------
// split KT + reversed-padded u windows into bf16 hi/lo
// ---------------------------------------------------------------------------
#define R1_SPLIT (256 * 128)
#define R2_SPLIT (NCHUNK * B_DIM * 256)
__global__ void k_split(const float* __restrict__ u) {
    int idx = blockIdx.x * 256 + threadIdx.x;
    if (idx < R1_SPLIT) {
        int i = idx >> 7, k = idx & 127;
        float x = g_K[k][i];
        __nv_bfloat16 h, l;
        split_bf16(x, h, l);
        g_KTh[i][k] = h;
        g_KTl[i][k] = l;
        return;
    }
    idx -= R1_SPLIT;
    if (idx < R2_SPLIT) {
        int c = idx >> 15;
        int b = (idx >> 8) & 127;
        int q = idx & 255;
        float x = (q <= 127) ? u[(c * CHK + 127 - q) * B_DIM + b] : 0.0f;
        __nv_bfloat16 h, l;
        split_bf16(x, h, l);
        g_uRh[c][b][q] = h;
        g_uRl[c][b][q] = l;
    }
}

// ---------------------------------------------------------------------------
// chunk-end conv (fp32): E_j[b][i] = sum_{k<128} Kvec[k][i] * u[j*128+127-k][b]
// ---------------------------------------------------------------------------
__device__ __forceinline__ void mm_compute16(const float (*Ast)[68], const float (*Bs)[66],
                                             float2 acc[4][2], int ty, int tx) {
#pragma unroll
    for (int kk = 0; kk < 16; kk++) {
        float2 b0 = *reinterpret_cast<const float2*>(&Bs[kk][tx * 4]);
        float2 b1 = *reinterpret_cast<const float2*>(&Bs[kk][tx * 4 + 2]);
#pragma unroll
        for (int ii = 0; ii < 4; ii++) {
            float a = Ast[kk][ty * 4 + ii];
            float2 a2 = make_float2(a, a);
            ffma2(acc[ii][0], a2, b0);
            ffma2(acc[ii][1], a2, b1);
        }
    }
}

__global__ void k_etail(const float* __restrict__ u) {
    int j = blockIdx.z;
    int b0 = blockIdx.y * 64, i0 = blockIdx.x * 64;
    __shared__ float Ast[16][68];
    __shared__ float Bs[16][66];
    int tid = threadIdx.x, tx = tid & 15, ty = tid >> 4;
    float2 acc[4][2] = {};

    for (int k0 = 0; k0 < CHK; k0 += 16) {
#pragma unroll
        for (int p = 0; p < 4; p++) {
            int idx = p * 256 + tid;
            int kk = idx >> 6, bb = idx & 63;
            Ast[kk][bb] = u[(j * CHK + 127 - (k0 + kk)) * B_DIM + b0 + bb];
        }
#pragma unroll
        for (int p = 0; p < 4; p++) {
            int idx = p * 256 + tid;
            int kk = idx >> 6, ii = idx & 63;
            Bs[kk][ii] = g_K[k0 + kk][i0 + ii];
        }
        __syncthreads();
        mm_compute16(Ast, Bs, acc, ty, tx);
        __syncthreads();
    }
#pragma unroll
    for (int ii = 0; ii < 4; ii++) {
        float4 v = make_float4(acc[ii][0].x, acc[ii][0].y, acc[ii][1].x, acc[ii][1].y);
        *reinterpret_cast<float4*>(&g_E[j][b0 + ty * 4 + ii][i0 + tx * 4]) = v;
    }
}

// ---------------------------------------------------------------------------
// single-launch sequential chunk scan:  X_0 = E_0 ; X_j = E_j + X_{j-1} @ P128^T
// register-prefetched P tiles.
// ---------------------------------------------------------------------------
__global__ void k_scanx() {
    __shared__ float s_cur[4][N_DIM];
    __shared__ float sP[N_DIM][33];
    int tid = threadIdx.x;
    int row = tid >> 6;
    int ic = tid & 63;
    int b = blockIdx.x * 4 + row;

#pragma unroll
    for (int m = 0; m < 4; m++) {
        int i = ic + m * 64;
        float v = g_E[0][b][i];
        s_cur[row][i] = v;
        __nv_bfloat16 h, l;
        split_bf16(v, h, l);
        g_Xh[1][b][i] = h;
        g_Xl[1][b][i] = l;
    }
    __syncthreads();

    float4 pf[8];
    auto g2r = [&](int kb) {
#pragma unroll
        for (int p = 0; p < 8; p++) {
            int e = p * 256 + tid;
            int rr = e >> 3, v = e & 7;
            pf[p] = *reinterpret_cast<const float4*>(&g_P[CHK][rr][kb * 32 + v * 4]);
        }
    };
    auto r2s = [&]() {
#pragma unroll
        for (int p = 0; p < 8; p++) {
            int e = p * 256 + tid;
            int rr = e >> 3, v = e & 7;
            sP[rr][v * 4 + 0] = pf[p].x;
            sP[rr][v * 4 + 1] = pf[p].y;
            sP[rr][v * 4 + 2] = pf[p].z;
            sP[rr][v * 4 + 3] = pf[p].w;
        }
    };

    for (int j = 1; j <= 14; j++) {
        float acc[4] = {0.f, 0.f, 0.f, 0.f};
        g2r(0);
#pragma unroll 1
        for (int kb = 0; kb < 8; kb++) {
            r2s();
            __syncthreads();
            if (kb < 7) g2r(kb + 1);
#pragma unroll
            for (int kk = 0; kk < 32; kk++) {
                float xv = s_cur[row][kb * 32 + kk];
#pragma unroll
                for (int m = 0; m < 4; m++)
                    acc[m] = fmaf(xv, sP[ic + m * 64][kk], acc[m]);
            }
            __syncthreads();
        }
#pragma unroll
        for (int m = 0; m < 4; m++) {
            int i = ic + m * 64;
            float v = g_E[j][b][i] + acc[m];
            s_cur[row][i] = v;
            __nv_bfloat16 h, l;
            split_bf16(v, h, l);
            g_Xh[j + 1][b][i] = h;
            g_Xl[j + 1][b][i] = l;
        }
        __syncthreads();
    }
}

// ---------------------------------------------------------------------------
// fused mma kernel v3: 2 CTAs per timestep (N-halves), K-chunk 32,
// zero-chunk skipping, 2 CTAs/SM, evict-first epilogue stores.
//   out[t](128 x 128-half) = [uR | X](128x384) @ [KT ; P[r+1]](n-half)
// 256 threads = 8 warps (4 wm x 2 wn), warp tile M32 x N64.
// ---------------------------------------------------------------------------
#define FST 80          // smem row stride bytes (32 bf16 = 64B + 16 pad)
#define ST_AH 0
#define ST_AL 10240
#define ST_BH 20480
#define ST_BL 30720
#define STAGE_B 40960
#define SMEM_FUSED (2 * STAGE_B)

__global__ void __launch_bounds__(256, 2) k_fused(float* __restrict__ out) {
    extern __shared__ char smbuf[];
    const uint32_t sb = smem_u32(smbuf);
    const int tid = threadIdx.x;
    const int lane = tid & 31, wid = tid >> 5;
    const int wm = wid & 3, wn = wid >> 2;        // 4 x 2 warp grid
    const int bx = blockIdx.x;
    const int r = bx >> 5;                        // 32 consecutive CTAs share P[r+1]
    const int c = (bx >> 1) & 15;
    const int bn = bx & 1;                        // N-half
    const int t = c * CHK + r;

    float acc[2][8][4];
#pragma unroll
    for (int ma = 0; ma < 2; ma++)
#pragma unroll
        for (int nb = 0; nb < 8; nb++)
#pragma unroll
            for (int q = 0; q < 4; q++) acc[ma][nb][q] = 0.f;

    // active chunk list: conv chunks 0..nc-1, X chunks 4..11 (if c>0)
    const int nc = (r >> 5) + 1;
    const int nact = nc + ((c > 0) ? 8 : 0);

    auto stage = [&](int li, int buf) {
        int kc = (li < nc) ? li : (li - nc + 4);
        uint32_t s0 = sb + buf * STAGE_B;
        char* c0 = smbuf + buf * STAGE_B;
        if (kc < 4) {
            // conv chunk: A = u window (synchronous, arbitrary shift), B = KT
            int q0 = 127 - r + kc * 32;
            if (!(q0 & 1)) {
#pragma unroll
                for (int it = 0; it < 2; it++) {
                    int e = it * 256 + tid;
                    int row = e >> 2, v = e & 3;
                    const uint32_t* ph = reinterpret_cast<const uint32_t*>(&g_uRh[c][row][q0 + v * 8]);
                    const uint32_t* pl = reinterpret_cast<const uint32_t*>(&g_uRl[c][row][q0 + v * 8]);
                    *reinterpret_cast<uint4*>(c0 + ST_AH + row * FST + v * 16) =
                        make_uint4(ph[0], ph[1], ph[2], ph[3]);
                    *reinterpret_cast<uint4*>(c0 + ST_AL + row * FST + v * 16) =
                        make_uint4(pl[0], pl[1], pl[2], pl[3]);
                }
            } else {
#pragma unroll
                for (int it = 0; it < 2; it++) {
                    int e = it * 256 + tid;
                    int row = e >> 2, v = e & 3;
                    uint32_t hw[4], lw[4];
#pragma unroll
                    for (int jq = 0; jq < 4; jq++) {
                        __nv_bfloat162 hv = make_bfloat162(g_uRh[c][row][q0 + v * 8 + 2 * jq],
                                                           g_uRh[c][row][q0 + v * 8 + 2 * jq + 1]);
                        __nv_bfloat162 lv = make_bfloat162(g_uRl[c][row][q0 + v * 8 + 2 * jq],
                                                           g_uRl[c][row][q0 + v * 8 + 2 * jq + 1]);
                        hw[jq] = *reinterpret_cast<uint32_t*>(&hv);
                        lw[jq] = *reinterpret_cast<uint32_t*>(&lv);
                    }
                    *reinterpret_cast<uint4*>(c0 + ST_AH + row * FST + v * 16) =
                        make_uint4(hw[0], hw[1], hw[2], hw[3]);
                    *reinterpret_cast<uint4*>(c0 + ST_AL + row * FST + v * 16) =
                        make_uint4(lw[0], lw[1], lw[2], lw[3]);
                }
            }
#pragma unroll
            for (int it = 0; it < 2; it++) {
                int e = it * 256 + tid;
                int row = e >> 2, v = e & 3;
                int n = bn * 128 + row;
                cp16(s0 + ST_BH + row * FST + v * 16, &g_KTh[n][kc * 32 + v * 8]);
                cp16(s0 + ST_BL + row * FST + v * 16, &g_KTl[n][kc * 32 + v * 8]);
            }
        } else {
            // X chunk: A = X splits, B = P[r+1] rows (n-half)
            int kb = (kc - 4) * 32;
#pragma unroll
            for (int it = 0; it < 2; it++) {
                int e = it * 256 + tid;
                int row = e >> 2, v = e & 3;
                cp16(s0 + ST_AH + row * FST + v * 16, &g_Xh[c][row][kb + v * 8]);
                cp16(s0 + ST_AL + row * FST + v * 16, &g_Xl[c][row][kb + v * 8]);
            }
#pragma unroll
            for (int it = 0; it < 2; it++) {
                int e = it * 256 + tid;
                int row = e >> 2, v = e & 3;
                int n = bn * 128 + row;
                cp16(s0 + ST_BH + row * FST + v * 16, &g_Ph[r + 1][n][kb + v * 8]);
                cp16(s0 + ST_BL + row * FST + v * 16, &g_Pl[r + 1][n][kb + v * 8]);
            }
        }
        cp_commit();
    };

    auto compute = [&](int buf) {
        uint32_t s0 = sb + buf * STAGE_B;
        uint32_t aA = s0 + ST_AH + (wm * 32 + (lane & 15)) * FST + (lane >> 4) * 16;
        uint32_t aB = s0 + ST_BH + (wn * 64 + (lane & 15)) * FST + (lane >> 4) * 16;
#pragma unroll
        for (int ks = 0; ks < 2; ks++) {
            uint32_t Ah[8], Al[8];
#pragma unroll
            for (int ma = 0; ma < 2; ma++) {
                ldsm4(&Ah[ma * 4], aA + ma * (16 * FST) + ks * 32);
                ldsm4(&Al[ma * 4], aA + (ST_AL - ST_AH) + ma * (16 * FST) + ks * 32);
            }
#pragma unroll
            for (int pr = 0; pr < 4; pr++) {
                uint32_t bh[4], bl[4];
                ldsm4(bh, aB + pr * (16 * FST) + ks * 32);
                ldsm4(bl, aB + (ST_BL - ST_BH) + pr * (16 * FST) + ks * 32);
#pragma unroll
                for (int sub = 0; sub < 2; sub++) {
                    int nb = pr * 2 + sub;
#pragma unroll
                    for (int ma = 0; ma < 2; ma++) {
                        mma_bf16(acc[ma][nb], &Ah[ma * 4], bh[sub], bh[2 + sub]);
                        mma_bf16(acc[ma][nb], &Ah[ma * 4], bl[sub], bl[2 + sub]);
                        mma_bf16(acc[ma][nb], &Al[ma * 4], bh[sub], bh[2 + sub]);
                    }
                }
            }
        }
    };

    stage(0, 0);
#pragma unroll 1
    for (int li = 0; li < nact; li++) {
        if (li + 1 < nact) stage(li + 1, (li + 1) & 1);
        if (li + 1 < nact) cp_wait<1>(); else cp_wait<0>();
        __syncthreads();
        compute(li & 1);
        __syncthreads();
    }

    // epilogue: evict-first fp32 stores (out never re-read; keep L2 clean)
    float* outt = out + (size_t)t * (B_DIM * N_DIM);
#pragma unroll
    for (int ma = 0; ma < 2; ma++) {
        int row = wm * 32 + ma * 16 + (lane >> 2);
#pragma unroll
        for (int nb = 0; nb < 8; nb++) {
            int col = bn * 128 + wn * 64 + nb * 8 + (lane & 3) * 2;
            __stcs(reinterpret_cast<float2*>(outt + row * 256 + col),
                   make_float2(acc[ma][nb][0], acc[ma][nb][1]));
            __stcs(reinterpret_cast<float2*>(outt + (row + 8) * 256 + col),
                   make_float2(acc[ma][nb][2], acc[ma][nb][3]));
        }
    }
}

// ---------------------------------------------------------------------------
extern "C" void kernel_launch(void* const* d_in, const int* in_sizes, int n_in,
                              void* d_out, int out_size) {
    const float* u  = (const float*)d_in[0];   // [L, B]
    const float* dA = (const float*)d_in[1];   // [N, N]
    const float* dB = (const float*)d_in[2];   // [N]
    float* out = (float*)d_out;                // [L, B, N]

    cudaFuncSetAttribute(k_fused, cudaFuncAttributeMaxDynamicSharedMemorySize, SMEM_FUSED);

    k_init<<<256, 256>>>(dA, dB);
    for (int m = 1; m < CHK; m <<= 1)
        k_power<<<dim3(4, 4, m), 256>>>(m);
    k_kvec<<<CHK - 1, 256>>>(dB);
    {
        int total = R1_SPLIT + R2_SPLIT;
        k_split<<<(total + 255) / 256, 256>>>(u);
    }
    k_etail<<<dim3(4, 2, NCHUNK), 256>>>(u);
    k_scanx<<<32, 256>>>();
    k_fused<<<2 * L_DIM, 256, SMEM_FUSED>>>(out);
}

// round 7
// speedup vs baseline: 4.1158x; 1.5039x over previous
#include <cuda_runtime.h>
#include <cuda_fp16.h>
#include <cstdint>

// Problem constants
#define N_DIM 256
#define L_DIM 2048
#define B_DIM 128
#define CHK   128
#define NCHUNK 16
#define PGRID 296

// ---------------------------------------------------------------------------
// Device global scratch
// ---------------------------------------------------------------------------
__device__ float g_P[CHK + 1][N_DIM][N_DIM];       // dA^p fp32, p = 1..128
__device__ float g_K[CHK][N_DIM];                  // Kvec fp32 (for etail)
__device__ float g_E[NCHUNK][B_DIM][N_DIM];        // chunk-end conv values
__device__ __half g_Pq[CHK + 1][N_DIM][N_DIM];     // fp16 P
__device__ __half g_KTq[N_DIM][CHK];               // fp16 K transposed
__device__ __half g_uRq[NCHUNK][B_DIM][256];       // fp16 reversed padded u
__device__ __half g_Xq[NCHUNK][B_DIM][N_DIM];      // fp16 X_{c-1} (c>=1)
__device__ unsigned g_barctr;

// ---------------------------------------------------------------------------
// helpers
// ---------------------------------------------------------------------------
__device__ __forceinline__ void ffma2(float2& c, float2 a, float2 b) {
    asm("{\n\t"
        ".reg .b64 ra, rb, rc;\n\t"
        "mov.b64 ra, {%2, %3};\n\t"
        "mov.b64 rb, {%4, %5};\n\t"
        "mov.b64 rc, {%0, %1};\n\t"
        "fma.rn.f32x2 rc, ra, rb, rc;\n\t"
        "mov.b64 {%0, %1}, rc;\n\t"
        "}"
        : "+f"(c.x), "+f"(c.y)
        : "f"(a.x), "f"(a.y), "f"(b.x), "f"(b.y));
}

__device__ __forceinline__ uint32_t smem_u32(const void* p) {
    uint32_t a;
    asm("{ .reg .u64 t; cvta.to.shared.u64 t, %1; cvt.u32.u64 %0, t; }" : "=r"(a) : "l"(p));
    return a;
}

__device__ __forceinline__ void mma_f16(float d[4], const uint32_t a[4],
                                        uint32_t b0, uint32_t b1) {
    asm volatile(
        "mma.sync.aligned.m16n8k16.row.col.f32.f16.f16.f32 "
        "{%0,%1,%2,%3}, {%4,%5,%6,%7}, {%8,%9}, {%0,%1,%2,%3};"
        : "+f"(d[0]), "+f"(d[1]), "+f"(d[2]), "+f"(d[3])
        : "r"(a[0]), "r"(a[1]), "r"(a[2]), "r"(a[3]), "r"(b0), "r"(b1));
}

__device__ __forceinline__ void ldsm4(uint32_t* r, uint32_t addr) {
    asm volatile("ldmatrix.sync.aligned.m8n8.x4.shared.b16 {%0,%1,%2,%3}, [%4];"
                 : "=r"(r[0]), "=r"(r[1]), "=r"(r[2]), "=r"(r[3]) : "r"(addr));
}

__device__ __forceinline__ void cp16(uint32_t sdst, const void* gsrc) {
    asm volatile("cp.async.cg.shared.global [%0], [%1], 16;" :: "r"(sdst), "l"(gsrc));
}
__device__ __forceinline__ void cp_commit() {
    asm volatile("cp.async.commit_group;" ::: "memory");
}
template <int NW>
__device__ __forceinline__ void cp_wait() {
    asm volatile("cp.async.wait_group %0;" :: "n"(NW) : "memory");
}

// grid-wide software barrier (monotonic counter; reset each replay in k_init)
__device__ __forceinline__ void gbar(unsigned target) {
    __syncthreads();
    if (threadIdx.x == 0) {
        __threadfence();
        atomicAdd(&g_barctr, 1u);
        unsigned v;
        do {
            asm volatile("ld.acquire.gpu.u32 %0, [%1];" : "=r"(v) : "l"(&g_barctr));
        } while (v < target);
    }
    __syncthreads();
}

// ---------------------------------------------------------------------------
// init: P[1] = dA (+ fp16), K[0] = dB, KT[:,0], barrier counter reset
// ---------------------------------------------------------------------------
__global__ void k_init(const float* __restrict__ dA, const float* __restrict__ dB) {
    int idx = blockIdx.x * 256 + threadIdx.x;
    if (idx == 0) g_barctr = 0u;
    if (idx < N_DIM * N_DIM) {
        float x = dA[idx];
        (&g_P[1][0][0])[idx] = x;
        (&g_Pq[1][0][0])[idx] = __float2half(x);
    }
    if (idx < N_DIM) {
        g_K[0][idx] = dB[idx];
        g_KTq[idx][0] = __float2half(dB[idx]);
    }
}

// ---------------------------------------------------------------------------
// single-launch power chain: 7 doubling phases with grid barrier, then
// tail: Kvec (fp32 + fp16 transposed) and reversed-u fp16 windows.
// ---------------------------------------------------------------------------
__global__ void __launch_bounds__(256, 2) k_powerall(const float* __restrict__ dB,
                                                     const float* __restrict__ u) {
    __shared__ __align__(16) float As[4][64][20];
    __shared__ __align__(16) float Bs[4][16][68];
    int tid = threadIdx.x, tx = tid & 15, ty = tid >> 4;

    for (int ph = 0; ph < 7; ph++) {
        int m = 1 << ph;
        int ntiles = 16 * m;
        for (int tile = blockIdx.x; tile < ntiles; tile += PGRID) {
            int j = (tile >> 4) + 1;
            int ti = tile & 15;
            int row0 = (ti >> 2) * 64, col0 = (ti & 3) * 64;
            const float* __restrict__ A = &g_P[j][0][0];
            const float* __restrict__ B = &g_P[m][0][0];
            float* __restrict__ C = &g_P[m + j][0][0];
            __half* __restrict__ Cq = &g_Pq[m + j][0][0];

            auto issue = [&](int kc) {
                int s = kc & 3;
                int k0 = kc * 16;
                {
                    int row = tid >> 2, v = tid & 3;
                    cp16(smem_u32(&As[s][row][v * 4]), &A[(row0 + row) * N_DIM + k0 + v * 4]);
                }
                {
                    int row = tid >> 4, v = tid & 15;
                    cp16(smem_u32(&Bs[s][row][v * 4]), &B[(k0 + row) * N_DIM + col0 + v * 4]);
                }
                cp_commit();
            };

            issue(0); issue(1); issue(2);
            float2 acc[4][2] = {};
#pragma unroll 1
            for (int kc = 0; kc < 16; kc++) {
                if (kc <= 13) cp_wait<2>();
                else if (kc == 14) cp_wait<1>();
                else cp_wait<0>();
                __syncthreads();
                if (kc + 3 < 16) issue(kc + 3);
                int s = kc & 3;
#pragma unroll
                for (int kk4 = 0; kk4 < 4; kk4++) {
                    float4 a4[4];
#pragma unroll
                    for (int ii = 0; ii < 4; ii++)
                        a4[ii] = *reinterpret_cast<const float4*>(&As[s][ty * 4 + ii][kk4 * 4]);
#pragma unroll
                    for (int q = 0; q < 4; q++) {
                        int kk = kk4 * 4 + q;
                        float2 b0 = *reinterpret_cast<const float2*>(&Bs[s][kk][tx * 4]);
                        float2 b1 = *reinterpret_cast<const float2*>(&Bs[s][kk][tx * 4 + 2]);
#pragma unroll
                        for (int ii = 0; ii < 4; ii++) {
                            float av = (q == 0) ? a4[ii].x : (q == 1) ? a4[ii].y
                                     : (q == 2) ? a4[ii].z : a4[ii].w;
                            float2 a2 = make_float2(av, av);
                            ffma2(acc[ii][0], a2, b0);
                            ffma2(acc[ii][1], a2, b1);
                        }
                    }
                }
            }
#pragma unroll
            for (int ii = 0; ii < 4; ii++) {
                int row = row0 + ty * 4 + ii, col = col0 + tx * 4;
                float4 v = make_float4(acc[ii][0].x, acc[ii][0].y, acc[ii][1].x, acc[ii][1].y);
                *reinterpret_cast<float4*>(&C[row * N_DIM + col]) = v;
                __half2 h01 = __floats2half2_rn(v.x, v.y);
                __half2 h23 = __floats2half2_rn(v.z, v.w);
                *reinterpret_cast<__half2*>(&Cq[row * N_DIM + col]) = h01;
                *reinterpret_cast<__half2*>(&Cq[row * N_DIM + col + 2]) = h23;
            }
            __syncthreads();
        }
        gbar(PGRID * (unsigned)(ph + 1));
    }

    // ---- tail: Kvec + uR conversion ----
    if (blockIdx.x < 127) {
        // K[k] = P[k] @ dB for k = blockIdx.x + 1; thread = output index i
        float* sDB = &As[0][0][0];
        sDB[tid] = dB[tid];
        __syncthreads();
        int k = blockIdx.x + 1;
        int i = tid;
        const float4* row4 = reinterpret_cast<const float4*>(&g_P[k][i][0]);
        const float4* sb4 = reinterpret_cast<const float4*>(sDB);
        float acc = 0.0f;
#pragma unroll 8
        for (int jj = 0; jj < N_DIM / 4; jj++) {
            float4 a = __ldcg(&row4[jj]);
            float4 b = sb4[jj];
            acc += a.x * b.x + a.y * b.y + a.z * b.z + a.w * b.w;
        }
        g_K[k][i] = acc;
        g_KTq[i][k] = __float2half(acc);
    } else {
        // reversed padded u -> fp16
        const int total = NCHUNK * B_DIM * 256;
        for (int idx = (blockIdx.x - 127) * 256 + tid; idx < total; idx += (PGRID - 127) * 256) {
            int c = idx >> 15;
            int b = (idx >> 8) & 127;
            int q = idx & 255;
            float x = (q <= 127) ? u[(c * CHK + 127 - q) * B_DIM + b] : 0.0f;
            g_uRq[c][b][q] = __float2half(x);
        }
    }
}

// ---------------------------------------------------------------------------
// chunk-end conv (fp32): E_j[b][i] = sum_{k<128} Kvec[k][i] * u[j*128+127-k][b]
// ---------------------------------------------------------------------------
__device__ __forceinline__ void mm_compute16(const float (*Ast)[68], const float (*Bs)[66],
                                             float2 acc[4][2], int ty, int tx) {
#pragma unroll
    for (int kk = 0; kk < 16; kk++) {
        float2 b0 = *reinterpret_cast<const float2*>(&Bs[kk][tx * 4]);
        float2 b1 = *reinterpret_cast<const float2*>(&Bs[kk][tx * 4 + 2]);
#pragma unroll
        for (int ii = 0; ii < 4; ii++) {
            float a = Ast[kk][ty * 4 + ii];
            float2 a2 = make_float2(a, a);
            ffma2(acc[ii][0], a2, b0);
            ffma2(acc[ii][1], a2, b1);
        }
    }
}

__global__ void k_etail(const float* __restrict__ u) {
    int j = blockIdx.z;
    int b0 = blockIdx.y * 64, i0 = blockIdx.x * 64;
    __shared__ float Ast[16][68];
    __shared__ float Bs[16][66];
    int tid = threadIdx.x, tx = tid & 15, ty = tid >> 4;
    float2 acc[4][2] = {};

    for (int k0 = 0; k0 < CHK; k0 += 16) {
#pragma unroll
        for (int p = 0; p < 4; p++) {
            int idx = p * 256 + tid;
            int kk = idx >> 6, bb = idx & 63;
            Ast[kk][bb] = u[(j * CHK + 127 - (k0 + kk)) * B_DIM + b0 + bb];
        }
#pragma unroll
        for (int p = 0; p < 4; p++) {
            int idx = p * 256 + tid;
            int kk = idx >> 6, ii = idx & 63;
            Bs[kk][ii] = g_K[k0 + kk][i0 + ii];
        }
        __syncthreads();
        mm_compute16(Ast, Bs, acc, ty, tx);
        __syncthreads();
    }
#pragma unroll
    for (int ii = 0; ii < 4; ii++) {
        float4 v = make_float4(acc[ii][0].x, acc[ii][0].y, acc[ii][1].x, acc[ii][1].y);
        *reinterpret_cast<float4*>(&g_E[j][b0 + ty * 4 + ii][i0 + tx * 4]) = v;
    }
}

// ---------------------------------------------------------------------------
// sequential chunk scan: X_0 = E_0 ; X_j = E_j + X_{j-1} @ P128^T  (fp32)
// epilogue writes fp16 X into g_Xq[j+1].
// ---------------------------------------------------------------------------
__global__ void k_scanx() {
    __shared__ float s_cur[4][N_DIM];
    __shared__ float sP[N_DIM][33];
    int tid = threadIdx.x;
    int row = tid >> 6;
    int ic = tid & 63;
    int b = blockIdx.x * 4 + row;

#pragma unroll
    for (int m = 0; m < 4; m++) {
        int i = ic + m * 64;
        float v = g_E[0][b][i];
        s_cur[row][i] = v;
        g_Xq[1][b][i] = __float2half(v);
    }
    __syncthreads();

    float4 pf[8];
    auto g2r = [&](int kb) {
#pragma unroll
        for (int p = 0; p < 8; p++) {
            int e = p * 256 + tid;
            int rr = e >> 3, v = e & 7;
            pf[p] = *reinterpret_cast<const float4*>(&g_P[CHK][rr][kb * 32 + v * 4]);
        }
    };
    auto r2s = [&]() {
#pragma unroll
        for (int p = 0; p < 8; p++) {
            int e = p * 256 + tid;
            int rr = e >> 3, v = e & 7;
            sP[rr][v * 4 + 0] = pf[p].x;
            sP[rr][v * 4 + 1] = pf[p].y;
            sP[rr][v * 4 + 2] = pf[p].z;
            sP[rr][v * 4 + 3] = pf[p].w;
        }
    };

    for (int j = 1; j <= 14; j++) {
        float acc[4] = {0.f, 0.f, 0.f, 0.f};
        g2r(0);
#pragma unroll 1
        for (int kb = 0; kb < 8; kb++) {
            r2s();
            __syncthreads();
            if (kb < 7) g2r(kb + 1);
#pragma unroll
            for (int kk = 0; kk < 32; kk++) {
                float xv = s_cur[row][kb * 32 + kk];
#pragma unroll
                for (int m = 0; m < 4; m++)
                    acc[m] = fmaf(xv, sP[ic + m * 64][kk], acc[m]);
            }
            __syncthreads();
        }
#pragma unroll
        for (int m = 0; m < 4; m++) {
            int i = ic + m * 64;
            float v = g_E[j][b][i] + acc[m];
            s_cur[row][i] = v;
            g_Xq[j + 1][b][i] = __float2half(v);
        }
        __syncthreads();
    }
}

// ---------------------------------------------------------------------------
// fused mma kernel v4 (fixed): fp16 single product. 2 CTAs per timestep,
// K-chunk 32, zero-chunk skipping, 2 CTAs/SM, evict-first stores.
// ---------------------------------------------------------------------------
#define FST 80          // smem row stride bytes (32 fp16 = 64B + 16 pad)
#define ST_B 10240
#define STAGE_B 20480
#define SMEM_FUSED (2 * STAGE_B)

__global__ void __launch_bounds__(256, 2) k_fused(float* __restrict__ out) {
    extern __shared__ char smbuf[];
    const uint32_t sb = smem_u32(smbuf);
    const int tid = threadIdx.x;
    const int lane = tid & 31, wid = tid >> 5;
    const int wm = wid & 3, wn = wid >> 2;        // 4 x 2 warp grid
    const int bx = blockIdx.x;
    const int r = bx >> 5;                        // 32 consecutive CTAs share P[r+1]
    const int c = (bx >> 1) & 15;
    const int bn = bx & 1;                        // N-half
    const int t = c * CHK + r;

    float acc[2][8][4];
#pragma unroll
    for (int ma = 0; ma < 2; ma++)
#pragma unroll
        for (int nb = 0; nb < 8; nb++)
#pragma unroll
            for (int q = 0; q < 4; q++) acc[ma][nb][q] = 0.f;

    const int nc = (r >> 5) + 1;                  // conv chunks
    const int nact = nc + ((c > 0) ? 8 : 0);      // + X chunks

    auto stage = [&](int li, int buf) {
        int kc = (li < nc) ? li : (li - nc + 4);
        uint32_t s0 = sb + buf * STAGE_B;
        char* c0 = smbuf + buf * STAGE_B;
        if (kc < 4) {
            // conv chunk: A = u window (synchronous, arbitrary shift), B = KT
            // A tile = 128 rows x 32 halfs = 128 x 16 uint32 -> 8 iters of 256
            int q0 = 127 - r + kc * 32;
            if (!(q0 & 1)) {
#pragma unroll
                for (int it = 0; it < 8; it++) {
                    int e = it * 256 + tid;
                    int row = e >> 4, v = e & 15;
                    *reinterpret_cast<uint32_t*>(c0 + row * FST + v * 4) =
                        *reinterpret_cast<const uint32_t*>(&g_uRq[c][row][q0 + v * 2]);
                }
            } else {
#pragma unroll
                for (int it = 0; it < 8; it++) {
                    int e = it * 256 + tid;
                    int row = e >> 4, v = e & 15;
                    __half2 hv = __halves2half2(g_uRq[c][row][q0 + v * 2],
                                                g_uRq[c][row][q0 + v * 2 + 1]);
                    *reinterpret_cast<__half2*>(c0 + row * FST + v * 4) = hv;
                }
            }
#pragma unroll
            for (int it = 0; it < 2; it++) {
                int e = it * 256 + tid;
                int row = e >> 2, v = e & 3;
                cp16(s0 + ST_B + row * FST + v * 16, &g_KTq[bn * 128 + row][kc * 32 + v * 8]);
            }
        } else {
            int kb = (kc - 4) * 32;
#pragma unroll
            for (int it = 0; it < 2; it++) {
                int e = it * 256 + tid;
                int row = e >> 2, v = e & 3;
                cp16(s0 + row * FST + v * 16, &g_Xq[c][row][kb + v * 8]);
            }
#pragma unroll
            for (int it = 0; it < 2; it++) {
                int e = it * 256 + tid;
                int row = e >> 2, v = e & 3;
                cp16(s0 + ST_B + row * FST + v * 16, &g_Pq[r + 1][bn * 128 + row][kb + v * 8]);
            }
        }
        cp_commit();
    };

    auto compute = [&](int buf) {
        uint32_t s0 = sb + buf * STAGE_B;
        uint32_t aA = s0 + (wm * 32 + (lane & 15)) * FST + (lane >> 4) * 16;
        uint32_t aB = s0 + ST_B + (wn * 64 + (lane & 15)) * FST + (lane >> 4) * 16;
#pragma unroll
        for (int ks = 0; ks < 2; ks++) {
            uint32_t Ah[8];
#pragma unroll
            for (int ma = 0; ma < 2; ma++)
                ldsm4(&Ah[ma * 4], aA + ma * (16 * FST) + ks * 32);
#pragma unroll
            for (int pr = 0; pr < 4; pr++) {
                uint32_t bh[4];
                ldsm4(bh, aB + pr * (16 * FST) + ks * 32);
#pragma unroll
                for (int sub = 0; sub < 2; sub++) {
                    int nb = pr * 2 + sub;
#pragma unroll
                    for (int ma = 0; ma < 2; ma++)
                        mma_f16(acc[ma][nb], &Ah[ma * 4], bh[sub], bh[2 + sub]);
                }
            }
        }
    };

    stage(0, 0);
#pragma unroll 1
    for (int li = 0; li < nact; li++) {
        if (li + 1 < nact) stage(li + 1, (li + 1) & 1);
        if (li + 1 < nact) cp_wait<1>(); else cp_wait<0>();
        __syncthreads();
        compute(li & 1);
        __syncthreads();
    }

    // epilogue: evict-first fp32 stores
    float* outt = out + (size_t)t * (B_DIM * N_DIM);
#pragma unroll
    for (int ma = 0; ma < 2; ma++) {
        int row = wm * 32 + ma * 16 + (lane >> 2);
#pragma unroll
        for (int nb = 0; nb < 8; nb++) {
            int col = bn * 128 + wn * 64 + nb * 8 + (lane & 3) * 2;
            __stcs(reinterpret_cast<float2*>(outt + row * 256 + col),
                   make_float2(acc[ma][nb][0], acc[ma][nb][1]));
            __stcs(reinterpret_cast<float2*>(outt + (row + 8) * 256 + col),
                   make_float2(acc[ma][nb][2], acc[ma][nb][3]));
        }
    }
}

// ---------------------------------------------------------------------------
extern "C" void kernel_launch(void* const* d_in, const int* in_sizes, int n_in,
                              void* d_out, int out_size) {
    const float* u  = (const float*)d_in[0];   // [L, B]
    const float* dA = (const float*)d_in[1];   // [N, N]
    const float* dB = (const float*)d_in[2];   // [N]
    float* out = (float*)d_out;                // [L, B, N]

    cudaFuncSetAttribute(k_fused, cudaFuncAttributeMaxDynamicSharedMemorySize, SMEM_FUSED);

    k_init<<<256, 256>>>(dA, dB);
    k_powerall<<<PGRID, 256>>>(dB, u);
    k_etail<<<dim3(4, 2, NCHUNK), 256>>>(u);
    k_scanx<<<32, 256>>>();
    k_fused<<<2 * L_DIM, 256, SMEM_FUSED>>>(out);
}

// round 8
// speedup vs baseline: 4.3366x; 1.0537x over previous
#include <cuda_runtime.h>
#include <cuda_fp16.h>
#include <cstdint>

// Problem constants
#define N_DIM 256
#define L_DIM 2048
#define B_DIM 128
#define CHK   128
#define NCHUNK 16
#define PGRID 296
#define XGRID 32

// ---------------------------------------------------------------------------
// Device global scratch
// ---------------------------------------------------------------------------
__device__ float g_P[CHK + 1][N_DIM][N_DIM];        // dA^p fp32, p = 1..128
__device__ float g_K[CHK][N_DIM];                   // Kvec fp32 (for etail)
__device__ float g_E[NCHUNK][B_DIM][N_DIM];         // chunk-end conv values
__device__ float g_Xf[2][B_DIM][N_DIM];             // fp32 X ping-pong (scan)
__device__ __half g_Pq[CHK + 1][N_DIM][N_DIM];      // fp16 P
__device__ __half g_KTq[N_DIM][CHK];                // fp16 K transposed
__device__ __half g_uRq8[8][NCHUNK][B_DIM][256];    // 8 byte-shift copies of reversed u
__device__ __half g_Xq[NCHUNK][B_DIM][N_DIM];       // fp16 X_{c-1} (c>=1)
__device__ unsigned g_barctr;
__device__ unsigned g_barctr2;

// ---------------------------------------------------------------------------
// helpers
// ---------------------------------------------------------------------------
__device__ __forceinline__ void ffma2(float2& c, float2 a, float2 b) {
    asm("{\n\t"
        ".reg .b64 ra, rb, rc;\n\t"
        "mov.b64 ra, {%2, %3};\n\t"
        "mov.b64 rb, {%4, %5};\n\t"
        "mov.b64 rc, {%0, %1};\n\t"
        "fma.rn.f32x2 rc, ra, rb, rc;\n\t"
        "mov.b64 {%0, %1}, rc;\n\t"
        "}"
        : "+f"(c.x), "+f"(c.y)
        : "f"(a.x), "f"(a.y), "f"(b.x), "f"(b.y));
}

__device__ __forceinline__ uint32_t smem_u32(const void* p) {
    uint32_t a;
    asm("{ .reg .u64 t; cvta.to.shared.u64 t, %1; cvt.u32.u64 %0, t; }" : "=r"(a) : "l"(p));
    return a;
}

__device__ __forceinline__ void mma_f16(float d[4], const uint32_t a[4],
                                        uint32_t b0, uint32_t b1) {
    asm volatile(
        "mma.sync.aligned.m16n8k16.row.col.f32.f16.f16.f32 "
        "{%0,%1,%2,%3}, {%4,%5,%6,%7}, {%8,%9}, {%0,%1,%2,%3};"
        : "+f"(d[0]), "+f"(d[1]), "+f"(d[2]), "+f"(d[3])
        : "r"(a[0]), "r"(a[1]), "r"(a[2]), "r"(a[3]), "r"(b0), "r"(b1));
}

__device__ __forceinline__ void ldsm4(uint32_t* r, uint32_t addr) {
    asm volatile("ldmatrix.sync.aligned.m8n8.x4.shared.b16 {%0,%1,%2,%3}, [%4];"
                 : "=r"(r[0]), "=r"(r[1]), "=r"(r[2]), "=r"(r[3]) : "r"(addr));
}

__device__ __forceinline__ void cp16(uint32_t sdst, const void* gsrc) {
    asm volatile("cp.async.cg.shared.global [%0], [%1], 16;" :: "r"(sdst), "l"(gsrc));
}
__device__ __forceinline__ void cp_commit() {
    asm volatile("cp.async.commit_group;" ::: "memory");
}
template <int NW>
__device__ __forceinline__ void cp_wait() {
    asm volatile("cp.async.wait_group %0;" :: "n"(NW) : "memory");
}

// grid-wide software barriers (monotonic counters; reset each replay in k_init)
__device__ __forceinline__ void gbar_on(unsigned* ctr, unsigned target) {
    __syncthreads();
    if (threadIdx.x == 0) {
        __threadfence();
        atomicAdd(ctr, 1u);
        unsigned v;
        do {
            asm volatile("ld.acquire.gpu.u32 %0, [%1];" : "=r"(v) : "l"(ctr));
        } while (v < target);
    }
    __syncthreads();
}

// ---------------------------------------------------------------------------
// init: P[1] = dA (+ fp16), K[0] = dB, KT[:,0], barrier counters reset
// ---------------------------------------------------------------------------
__global__ void k_init(const float* __restrict__ dA, const float* __restrict__ dB) {
    int idx = blockIdx.x * 256 + threadIdx.x;
    if (idx == 0) { g_barctr = 0u; g_barctr2 = 0u; }
    if (idx < N_DIM * N_DIM) {
        float x = dA[idx];
        (&g_P[1][0][0])[idx] = x;
        (&g_Pq[1][0][0])[idx] = __float2half(x);
    }
    if (idx < N_DIM) {
        g_K[0][idx] = dB[idx];
        g_KTq[idx][0] = __float2half(dB[idx]);
    }
}

// ---------------------------------------------------------------------------
// single-launch power chain: 7 doubling phases with grid barrier, then
// tail: Kvec (fp32 + fp16 transposed) and 8 shifted reversed-u fp16 copies.
// ---------------------------------------------------------------------------
__global__ void __launch_bounds__(256, 2) k_powerall(const float* __restrict__ dB,
                                                     const float* __restrict__ u) {
    __shared__ __align__(16) float As[4][64][20];
    __shared__ __align__(16) float Bs[4][16][68];
    int tid = threadIdx.x, tx = tid & 15, ty = tid >> 4;

    for (int ph = 0; ph < 7; ph++) {
        int m = 1 << ph;
        int ntiles = 16 * m;
        for (int tile = blockIdx.x; tile < ntiles; tile += PGRID) {
            int j = (tile >> 4) + 1;
            int ti = tile & 15;
            int row0 = (ti >> 2) * 64, col0 = (ti & 3) * 64;
            const float* __restrict__ A = &g_P[j][0][0];
            const float* __restrict__ B = &g_P[m][0][0];
            float* __restrict__ C = &g_P[m + j][0][0];
            __half* __restrict__ Cq = &g_Pq[m + j][0][0];

            auto issue = [&](int kc) {
                int s = kc & 3;
                int k0 = kc * 16;
                {
                    int row = tid >> 2, v = tid & 3;
                    cp16(smem_u32(&As[s][row][v * 4]), &A[(row0 + row) * N_DIM + k0 + v * 4]);
                }
                {
                    int row = tid >> 4, v = tid & 15;
                    cp16(smem_u32(&Bs[s][row][v * 4]), &B[(k0 + row) * N_DIM + col0 + v * 4]);
                }
                cp_commit();
            };

            issue(0); issue(1); issue(2);
            float2 acc[4][2] = {};
#pragma unroll 1
            for (int kc = 0; kc < 16; kc++) {
                if (kc <= 13) cp_wait<2>();
                else if (kc == 14) cp_wait<1>();
                else cp_wait<0>();
                __syncthreads();
                if (kc + 3 < 16) issue(kc + 3);
                int s = kc & 3;
#pragma unroll
                for (int kk4 = 0; kk4 < 4; kk4++) {
                    float4 a4[4];
#pragma unroll
                    for (int ii = 0; ii < 4; ii++)
                        a4[ii] = *reinterpret_cast<const float4*>(&As[s][ty * 4 + ii][kk4 * 4]);
#pragma unroll
                    for (int q = 0; q < 4; q++) {
                        int kk = kk4 * 4 + q;
                        float2 b0 = *reinterpret_cast<const float2*>(&Bs[s][kk][tx * 4]);
                        float2 b1 = *reinterpret_cast<const float2*>(&Bs[s][kk][tx * 4 + 2]);
#pragma unroll
                        for (int ii = 0; ii < 4; ii++) {
                            float av = (q == 0) ? a4[ii].x : (q == 1) ? a4[ii].y
                                     : (q == 2) ? a4[ii].z : a4[ii].w;
                            float2 a2 = make_float2(av, av);
                            ffma2(acc[ii][0], a2, b0);
                            ffma2(acc[ii][1], a2, b1);
                        }
                    }
                }
            }
#pragma unroll
            for (int ii = 0; ii < 4; ii++) {
                int row = row0 + ty * 4 + ii, col = col0 + tx * 4;
                float4 v = make_float4(acc[ii][0].x, acc[ii][0].y, acc[ii][1].x, acc[ii][1].y);
                *reinterpret_cast<float4*>(&C[row * N_DIM + col]) = v;
                __half2 h01 = __floats2half2_rn(v.x, v.y);
                __half2 h23 = __floats2half2_rn(v.z, v.w);
                *reinterpret_cast<__half2*>(&Cq[row * N_DIM + col]) = h01;
                *reinterpret_cast<__half2*>(&Cq[row * N_DIM + col + 2]) = h23;
            }
            __syncthreads();
        }
        gbar_on(&g_barctr, PGRID * (unsigned)(ph + 1));
    }

    // ---- tail: Kvec + 8 shifted uR copies ----
    if (blockIdx.x < 127) {
        float* sDB = &As[0][0][0];
        sDB[tid] = dB[tid];
        __syncthreads();
        int k = blockIdx.x + 1;
        int i = tid;
        const float4* row4 = reinterpret_cast<const float4*>(&g_P[k][i][0]);
        const float4* sb4 = reinterpret_cast<const float4*>(sDB);
        float acc = 0.0f;
#pragma unroll 8
        for (int jj = 0; jj < N_DIM / 4; jj++) {
            float4 a = __ldcg(&row4[jj]);
            float4 b = sb4[jj];
            acc += a.x * b.x + a.y * b.y + a.z * b.z + a.w * b.w;
        }
        g_K[k][i] = acc;
        g_KTq[i][k] = __float2half(acc);
    } else {
        // 8 shifted reversed-u copies: g_uRq8[s][c][b][x] = uR(x + s)
        const int total8 = 8 * NCHUNK * B_DIM * 256;
        for (int idx = (blockIdx.x - 127) * 256 + tid; idx < total8;
             idx += (PGRID - 127) * 256) {
            int s = idx >> 19;
            int rem = idx & ((1 << 19) - 1);
            int c = rem >> 15;
            int b = (rem >> 8) & 127;
            int x = rem & 255;
            int q = x + s;
            float v = (q <= 127) ? u[(c * CHK + 127 - q) * B_DIM + b] : 0.0f;
            g_uRq8[s][c][b][x] = __float2half(v);
        }
    }
}

// ---------------------------------------------------------------------------
// chunk-end conv (fp32): E_j[b][i] = sum_{k<128} Kvec[k][i] * u[j*128+127-k][b]
// ---------------------------------------------------------------------------
__device__ __forceinline__ void mm_compute16(const float (*Ast)[68], const float (*Bs)[66],
                                             float2 acc[4][2], int ty, int tx) {
#pragma unroll
    for (int kk = 0; kk < 16; kk++) {
        float2 b0 = *reinterpret_cast<const float2*>(&Bs[kk][tx * 4]);
        float2 b1 = *reinterpret_cast<const float2*>(&Bs[kk][tx * 4 + 2]);
#pragma unroll
        for (int ii = 0; ii < 4; ii++) {
            float a = Ast[kk][ty * 4 + ii];
            float2 a2 = make_float2(a, a);
            ffma2(acc[ii][0], a2, b0);
            ffma2(acc[ii][1], a2, b1);
        }
    }
}

__global__ void k_etail(const float* __restrict__ u) {
    int j = blockIdx.z;
    int b0 = blockIdx.y * 64, i0 = blockIdx.x * 64;
    __shared__ float Ast[16][68];
    __shared__ float Bs[16][66];
    int tid = threadIdx.x, tx = tid & 15, ty = tid >> 4;
    float2 acc[4][2] = {};

    for (int k0 = 0; k0 < CHK; k0 += 16) {
#pragma unroll
        for (int p = 0; p < 4; p++) {
            int idx = p * 256 + tid;
            int kk = idx >> 6, bb = idx & 63;
            Ast[kk][bb] = u[(j * CHK + 127 - (k0 + kk)) * B_DIM + b0 + bb];
        }
#pragma unroll
        for (int p = 0; p < 4; p++) {
            int idx = p * 256 + tid;
            int kk = idx >> 6, ii = idx & 63;
            Bs[kk][ii] = g_K[k0 + kk][i0 + ii];
        }
        __syncthreads();
        mm_compute16(Ast, Bs, acc, ty, tx);
        __syncthreads();
    }
#pragma unroll
    for (int ii = 0; ii < 4; ii++) {
        float4 v = make_float4(acc[ii][0].x, acc[ii][0].y, acc[ii][1].x, acc[ii][1].y);
        *reinterpret_cast<float4*>(&g_E[j][b0 + ty * 4 + ii][i0 + tx * 4]) = v;
    }
}

// ---------------------------------------------------------------------------
// scan v2: P128 slice RESIDENT in smem, grid barrier between steps.
// 32 CTAs: tile 32b x 32i. X fp32 ping-pong in global; fp16 X to g_Xq.
// ---------------------------------------------------------------------------
#define SCAN_SMEM (256 * 34 * 4 + 32 * 260 * 4)
__global__ void __launch_bounds__(256, 1) k_scanx2() {
    extern __shared__ float sx[];
    float (*Psm)[34] = reinterpret_cast<float(*)[34]>(sx);             // [k 256][ic 32]
    float (*Xs)[260] = reinterpret_cast<float(*)[260]>(sx + 256 * 34); // [b 32][k 256]
    int tid = threadIdx.x;
    int b0 = (blockIdx.x >> 3) * 32;
    int i0 = (blockIdx.x & 7) * 32;

    // persistent P slice: Psm[k][ir] = P128[i0+ir][k]
#pragma unroll
    for (int it = 0; it < 8; it++) {
        int e = it * 256 + tid;
        int ir = e >> 6, v = e & 63;
        float4 x = *reinterpret_cast<const float4*>(&g_P[CHK][i0 + ir][v * 4]);
        Psm[v * 4 + 0][ir] = x.x;
        Psm[v * 4 + 1][ir] = x.y;
        Psm[v * 4 + 2][ir] = x.z;
        Psm[v * 4 + 3][ir] = x.w;
    }
    // X_0 = E_0 tile
    {
        int r = tid >> 3, v = tid & 7;
        float4 e0 = *reinterpret_cast<const float4*>(&g_E[0][b0 + r][i0 + v * 4]);
        *reinterpret_cast<float4*>(&g_Xf[0][b0 + r][i0 + v * 4]) = e0;
        __half2 h0 = __floats2half2_rn(e0.x, e0.y);
        __half2 h1 = __floats2half2_rn(e0.z, e0.w);
        *reinterpret_cast<__half2*>(&g_Xq[1][b0 + r][i0 + v * 4]) = h0;
        *reinterpret_cast<__half2*>(&g_Xq[1][b0 + r][i0 + v * 4 + 2]) = h1;
    }
    gbar_on(&g_barctr2, XGRID);

    int ty = tid >> 3, tx = tid & 7;   // row 0..31, colgrp 0..7 (x4)
    for (int j = 1; j <= 14; j++) {
        const float* src = &g_Xf[(j - 1) & 1][0][0];
#pragma unroll
        for (int it = 0; it < 8; it++) {
            int e = it * 256 + tid;
            int r = e >> 6, v = e & 63;
            float4 x = *reinterpret_cast<const float4*>(src + (b0 + r) * N_DIM + v * 4);
            *reinterpret_cast<float4*>(&Xs[r][v * 4]) = x;
        }
        __syncthreads();
        float2 c0 = make_float2(0.f, 0.f), c1 = make_float2(0.f, 0.f);
#pragma unroll 4
        for (int k = 0; k < 256; k++) {
            float2 p0 = *reinterpret_cast<const float2*>(&Psm[k][tx * 4]);
            float2 p1 = *reinterpret_cast<const float2*>(&Psm[k][tx * 4 + 2]);
            float a = Xs[ty][k];
            float2 a2 = make_float2(a, a);
            ffma2(c0, a2, p0);
            ffma2(c1, a2, p1);
        }
        float4 ej = *reinterpret_cast<const float4*>(&g_E[j][b0 + ty][i0 + tx * 4]);
        float4 xv = make_float4(ej.x + c0.x, ej.y + c0.y, ej.z + c1.x, ej.w + c1.y);
        *reinterpret_cast<float4*>(&g_Xf[j & 1][b0 + ty][i0 + tx * 4]) = xv;
        __half2 h0 = __floats2half2_rn(xv.x, xv.y);
        __half2 h1 = __floats2half2_rn(xv.z, xv.w);
        *reinterpret_cast<__half2*>(&g_Xq[j + 1][b0 + ty][i0 + tx * 4]) = h0;
        *reinterpret_cast<__half2*>(&g_Xq[j + 1][b0 + ty][i0 + tx * 4 + 2]) = h1;
        gbar_on(&g_barctr2, XGRID * (unsigned)(j + 1));
    }
}

// ---------------------------------------------------------------------------
// fused mma kernel v5: fp16 single product, 4-deep cp.async ring, all-async
// staging (8 shifted uR copies give 16B alignment), 1 sync per chunk.
// 2 CTAs per timestep (N-halves), K-chunk 32, zero-chunk skipping, stcs.
// ---------------------------------------------------------------------------
#define FST 80          // smem row stride bytes (32 fp16 = 64B + 16 pad)
#define ST_B 10240
#define STAGE_B 20480
#define SMEM_FUSED (4 * STAGE_B)

__global__ void __launch_bounds__(256, 2) k_fused(float* __restrict__ out) {
    extern __shared__ char smbuf[];
    const uint32_t sb = smem_u32(smbuf);
    const int tid = threadIdx.x;
    const int lane = tid & 31, wid = tid >> 5;
    const int wm = wid & 3, wn = wid >> 2;        // 4 x 2 warp grid
    const int bx = blockIdx.x;
    const int r = bx >> 5;                        // 32 consecutive CTAs share P[r+1]
    const int c = (bx >> 1) & 15;
    const int bn = bx & 1;                        // N-half
    const int t = c * CHK + r;

    float acc[2][8][4];
#pragma unroll
    for (int ma = 0; ma < 2; ma++)
#pragma unroll
        for (int nb = 0; nb < 8; nb++)
#pragma unroll
            for (int q = 0; q < 4; q++) acc[ma][nb][q] = 0.f;

    const int nc = (r >> 5) + 1;                  // conv chunks
    const int nact = nc + ((c > 0) ? 8 : 0);      // + X chunks
    const int s8 = (127 - r) & 7;
    const int xbase = 127 - r - s8;               // 8-aligned

    auto stage = [&](int li) {
        int buf = li & 3;
        int kc = (li < nc) ? li : (li - nc + 4);
        uint32_t s0 = sb + buf * STAGE_B;
        if (kc < 4) {
            int x0 = xbase + kc * 32;
#pragma unroll
            for (int it = 0; it < 2; it++) {
                int e = it * 256 + tid;
                int row = e >> 2, v = e & 3;
                cp16(s0 + row * FST + v * 16, &g_uRq8[s8][c][row][x0 + v * 8]);
            }
#pragma unroll
            for (int it = 0; it < 2; it++) {
                int e = it * 256 + tid;
                int row = e >> 2, v = e & 3;
                cp16(s0 + ST_B + row * FST + v * 16, &g_KTq[bn * 128 + row][kc * 32 + v * 8]);
            }
        } else {
            int kb = (kc - 4) * 32;
#pragma unroll
            for (int it = 0; it < 2; it++) {
                int e = it * 256 + tid;
                int row = e >> 2, v = e & 3;
                cp16(s0 + row * FST + v * 16, &g_Xq[c][row][kb + v * 8]);
            }
#pragma unroll
            for (int it = 0; it < 2; it++) {
                int e = it * 256 + tid;
                int row = e >> 2, v = e & 3;
                cp16(s0 + ST_B + row * FST + v * 16, &g_Pq[r + 1][bn * 128 + row][kb + v * 8]);
            }
        }
        cp_commit();
    };

    auto compute = [&](int buf) {
        uint32_t s0 = sb + buf * STAGE_B;
        uint32_t aA = s0 + (wm * 32 + (lane & 15)) * FST + (lane >> 4) * 16;
        uint32_t aB = s0 + ST_B + (wn * 64 + (lane & 15)) * FST + (lane >> 4) * 16;
#pragma unroll
        for (int ks = 0; ks < 2; ks++) {
            uint32_t Ah[8];
#pragma unroll
            for (int ma = 0; ma < 2; ma++)
                ldsm4(&Ah[ma * 4], aA + ma * (16 * FST) + ks * 32);
#pragma unroll
            for (int pr = 0; pr < 4; pr++) {
                uint32_t bh[4];
                ldsm4(bh, aB + pr * (16 * FST) + ks * 32);
#pragma unroll
                for (int sub = 0; sub < 2; sub++) {
                    int nb = pr * 2 + sub;
#pragma unroll
                    for (int ma = 0; ma < 2; ma++)
                        mma_f16(acc[ma][nb], &Ah[ma * 4], bh[sub], bh[2 + sub]);
                }
            }
        }
    };

    if (0 < nact) stage(0);
    if (1 < nact) stage(1);
    if (2 < nact) stage(2);
#pragma unroll 1
    for (int li = 0; li < nact; li++) {
        int ahead = nact - 1 - li;
        if (ahead >= 2) cp_wait<2>();
        else if (ahead == 1) cp_wait<1>();
        else cp_wait<0>();
        __syncthreads();
        if (li + 3 < nact) stage(li + 3);
        compute(li & 3);
    }

    // epilogue: evict-first fp32 stores
    float* outt = out + (size_t)t * (B_DIM * N_DIM);
#pragma unroll
    for (int ma = 0; ma < 2; ma++) {
        int row = wm * 32 + ma * 16 + (lane >> 2);
#pragma unroll
        for (int nb = 0; nb < 8; nb++) {
            int col = bn * 128 + wn * 64 + nb * 8 + (lane & 3) * 2;
            __stcs(reinterpret_cast<float2*>(outt + row * 256 + col),
                   make_float2(acc[ma][nb][0], acc[ma][nb][1]));
            __stcs(reinterpret_cast<float2*>(outt + (row + 8) * 256 + col),
                   make_float2(acc[ma][nb][2], acc[ma][nb][3]));
        }
    }
}

// ---------------------------------------------------------------------------
extern "C" void kernel_launch(void* const* d_in, const int* in_sizes, int n_in,
                              void* d_out, int out_size) {
    const float* u  = (const float*)d_in[0];   // [L, B]
    const float* dA = (const float*)d_in[1];   // [N, N]
    const float* dB = (const float*)d_in[2];   // [N]
    float* out = (float*)d_out;                // [L, B, N]

    cudaFuncSetAttribute(k_fused, cudaFuncAttributeMaxDynamicSharedMemorySize, SMEM_FUSED);
    cudaFuncSetAttribute(k_scanx2, cudaFuncAttributeMaxDynamicSharedMemorySize, SCAN_SMEM);

    k_init<<<256, 256>>>(dA, dB);
    k_powerall<<<PGRID, 256>>>(dB, u);
    k_etail<<<dim3(4, 2, NCHUNK), 256>>>(u);
    k_scanx2<<<XGRID, 256, SCAN_SMEM>>>();
    k_fused<<<2 * L_DIM, 256, SMEM_FUSED>>>(out);
}

// round 9
// speedup vs baseline: 4.5134x; 1.0408x over previous
#include <cuda_runtime.h>
#include <cuda_fp16.h>
#include <cstdint>

// Problem constants
#define N_DIM 256
#define L_DIM 2048
#define B_DIM 128
#define CHK   128
#define NCHUNK 16
#define PGRID 296
#define XGRID 64

// ---------------------------------------------------------------------------
// Device global scratch
// ---------------------------------------------------------------------------
__device__ float g_P[CHK + 1][N_DIM][N_DIM];        // dA^p fp32, p = 1..128
__device__ float g_P2[N_DIM][N_DIM];                // dA^256 fp32 (T^2 operand)
__device__ float g_K[CHK][N_DIM];                   // Kvec fp32 (for etail)
__device__ float g_E[NCHUNK][B_DIM][N_DIM];         // chunk-end conv values
__device__ float g_F[NCHUNK][B_DIM][N_DIM];         // F_j = E_j + E_{j-1} T
__device__ float g_Xf[2][2][B_DIM][N_DIM];          // fp32 X ping-pong per parity
__device__ __half g_Pq[CHK + 1][N_DIM][N_DIM];      // fp16 P
__device__ __half g_KTq[N_DIM][CHK];                // fp16 K transposed
__device__ __half g_uRq8[8][NCHUNK][B_DIM][256];    // 8 byte-shift copies of reversed u
__device__ __half g_Xq[NCHUNK][B_DIM][N_DIM];       // fp16 X_{c-1} (c>=1)
__device__ unsigned g_barctr;
__device__ unsigned g_barctr2;

// ---------------------------------------------------------------------------
// helpers
// ---------------------------------------------------------------------------
__device__ __forceinline__ void ffma2(float2& c, float2 a, float2 b) {
    asm("{\n\t"
        ".reg .b64 ra, rb, rc;\n\t"
        "mov.b64 ra, {%2, %3};\n\t"
        "mov.b64 rb, {%4, %5};\n\t"
        "mov.b64 rc, {%0, %1};\n\t"
        "fma.rn.f32x2 rc, ra, rb, rc;\n\t"
        "mov.b64 {%0, %1}, rc;\n\t"
        "}"
        : "+f"(c.x), "+f"(c.y)
        : "f"(a.x), "f"(a.y), "f"(b.x), "f"(b.y));
}

__device__ __forceinline__ uint32_t smem_u32(const void* p) {
    uint32_t a;
    asm("{ .reg .u64 t; cvta.to.shared.u64 t, %1; cvt.u32.u64 %0, t; }" : "=r"(a) : "l"(p));
    return a;
}

__device__ __forceinline__ void mma_f16(float d[4], const uint32_t a[4],
                                        uint32_t b0, uint32_t b1) {
    asm volatile(
        "mma.sync.aligned.m16n8k16.row.col.f32.f16.f16.f32 "
        "{%0,%1,%2,%3}, {%4,%5,%6,%7}, {%8,%9}, {%0,%1,%2,%3};"
        : "+f"(d[0]), "+f"(d[1]), "+f"(d[2]), "+f"(d[3])
        : "r"(a[0]), "r"(a[1]), "r"(a[2]), "r"(a[3]), "r"(b0), "r"(b1));
}

__device__ __forceinline__ void ldsm4(uint32_t* r, uint32_t addr) {
    asm volatile("ldmatrix.sync.aligned.m8n8.x4.shared.b16 {%0,%1,%2,%3}, [%4];"
                 : "=r"(r[0]), "=r"(r[1]), "=r"(r[2]), "=r"(r[3]) : "r"(addr));
}

__device__ __forceinline__ void cp16(uint32_t sdst, const void* gsrc) {
    asm volatile("cp.async.cg.shared.global [%0], [%1], 16;" :: "r"(sdst), "l"(gsrc));
}
__device__ __forceinline__ void cp_commit() {
    asm volatile("cp.async.commit_group;" ::: "memory");
}
template <int NW>
__device__ __forceinline__ void cp_wait() {
    asm volatile("cp.async.wait_group %0;" :: "n"(NW) : "memory");
}

// grid-wide software barriers (monotonic counters; reset each replay in k_init)
__device__ __forceinline__ void gbar_on(unsigned* ctr, unsigned target) {
    __syncthreads();
    if (threadIdx.x == 0) {
        __threadfence();
        atomicAdd(ctr, 1u);
        unsigned v;
        do {
            asm volatile("ld.acquire.gpu.u32 %0, [%1];" : "=r"(v) : "l"(ctr));
        } while (v < target);
    }
    __syncthreads();
}

// ---------------------------------------------------------------------------
// init: P[1] = dA (+ fp16), K[0] = dB, KT[:,0], barrier counters reset
// ---------------------------------------------------------------------------
__global__ void k_init(const float* __restrict__ dA, const float* __restrict__ dB) {
    int idx = blockIdx.x * 256 + threadIdx.x;
    if (idx == 0) { g_barctr = 0u; g_barctr2 = 0u; }
    if (idx < N_DIM * N_DIM) {
        float x = dA[idx];
        (&g_P[1][0][0])[idx] = x;
        (&g_Pq[1][0][0])[idx] = __float2half(x);
    }
    if (idx < N_DIM) {
        g_K[0][idx] = dB[idx];
        g_KTq[idx][0] = __float2half(dB[idx]);
    }
}

// ---------------------------------------------------------------------------
// fp32 64x64x256 NN GEMM tile (cp.async 4-stage ring); optional fp16 mirror
// ---------------------------------------------------------------------------
__device__ __forceinline__ void gemm_tile_f32(
    const float* __restrict__ A, const float* __restrict__ B,
    float* __restrict__ C, __half* __restrict__ Cq,
    int row0, int col0,
    float (*As)[64][20], float (*Bs)[16][68],
    int tid, int tx, int ty
) {
    auto issue = [&](int kc) {
        int s = kc & 3;
        int k0 = kc * 16;
        {
            int row = tid >> 2, v = tid & 3;
            cp16(smem_u32(&As[s][row][v * 4]), &A[(row0 + row) * N_DIM + k0 + v * 4]);
        }
        {
            int row = tid >> 4, v = tid & 15;
            cp16(smem_u32(&Bs[s][row][v * 4]), &B[(k0 + row) * N_DIM + col0 + v * 4]);
        }
        cp_commit();
    };

    issue(0); issue(1); issue(2);
    float2 acc[4][2] = {};
#pragma unroll 1
    for (int kc = 0; kc < 16; kc++) {
        if (kc <= 13) cp_wait<2>();
        else if (kc == 14) cp_wait<1>();
        else cp_wait<0>();
        __syncthreads();
        if (kc + 3 < 16) issue(kc + 3);
        int s = kc & 3;
#pragma unroll
        for (int kk4 = 0; kk4 < 4; kk4++) {
            float4 a4[4];
#pragma unroll
            for (int ii = 0; ii < 4; ii++)
                a4[ii] = *reinterpret_cast<const float4*>(&As[s][ty * 4 + ii][kk4 * 4]);
#pragma unroll
            for (int q = 0; q < 4; q++) {
                int kk = kk4 * 4 + q;
                float2 b0 = *reinterpret_cast<const float2*>(&Bs[s][kk][tx * 4]);
                float2 b1 = *reinterpret_cast<const float2*>(&Bs[s][kk][tx * 4 + 2]);
#pragma unroll
                for (int ii = 0; ii < 4; ii++) {
                    float av = (q == 0) ? a4[ii].x : (q == 1) ? a4[ii].y
                             : (q == 2) ? a4[ii].z : a4[ii].w;
                    float2 a2 = make_float2(av, av);
                    ffma2(acc[ii][0], a2, b0);
                    ffma2(acc[ii][1], a2, b1);
                }
            }
        }
    }
#pragma unroll
    for (int ii = 0; ii < 4; ii++) {
        int row = row0 + ty * 4 + ii, col = col0 + tx * 4;
        float4 v = make_float4(acc[ii][0].x, acc[ii][0].y, acc[ii][1].x, acc[ii][1].y);
        *reinterpret_cast<float4*>(&C[row * N_DIM + col]) = v;
        if (Cq) {
            __half2 h01 = __floats2half2_rn(v.x, v.y);
            __half2 h23 = __floats2half2_rn(v.z, v.w);
            *reinterpret_cast<__half2*>(&Cq[row * N_DIM + col]) = h01;
            *reinterpret_cast<__half2*>(&Cq[row * N_DIM + col + 2]) = h23;
        }
    }
    __syncthreads();
}

// ---------------------------------------------------------------------------
// single-launch power chain: 7 doubling phases + P256, then tail
// (Kvec fp32+fp16T, 8 shifted reversed-u fp16 copies).
// ---------------------------------------------------------------------------
__global__ void __launch_bounds__(256, 2) k_powerall(const float* __restrict__ dB,
                                                     const float* __restrict__ u) {
    __shared__ __align__(16) float As[4][64][20];
    __shared__ __align__(16) float Bs[4][16][68];
    int tid = threadIdx.x, tx = tid & 15, ty = tid >> 4;

    for (int ph = 0; ph < 7; ph++) {
        int m = 1 << ph;
        int ntiles = 16 * m;
        for (int tile = blockIdx.x; tile < ntiles; tile += PGRID) {
            int j = (tile >> 4) + 1;
            int ti = tile & 15;
            gemm_tile_f32(&g_P[j][0][0], &g_P[m][0][0],
                          &g_P[m + j][0][0], &g_Pq[m + j][0][0],
                          (ti >> 2) * 64, (ti & 3) * 64, As, Bs, tid, tx, ty);
        }
        gbar_on(&g_barctr, PGRID * (unsigned)(ph + 1));
    }

    // P256 = P128 @ P128 (fp32 only; used as T^2 in the parity scan)
    if (blockIdx.x < 16) {
        int ti = blockIdx.x;
        gemm_tile_f32(&g_P[CHK][0][0], &g_P[CHK][0][0], &g_P2[0][0], nullptr,
                      (ti >> 2) * 64, (ti & 3) * 64, As, Bs, tid, tx, ty);
    }

    // ---- tail: Kvec + 8 shifted uR copies ----
    if (blockIdx.x < 127) {
        float* sDB = &As[0][0][0];
        sDB[tid] = dB[tid];
        __syncthreads();
        int k = blockIdx.x + 1;
        int i = tid;
        const float4* row4 = reinterpret_cast<const float4*>(&g_P[k][i][0]);
        const float4* sb4 = reinterpret_cast<const float4*>(sDB);
        float acc = 0.0f;
#pragma unroll 8
        for (int jj = 0; jj < N_DIM / 4; jj++) {
            float4 a = __ldcg(&row4[jj]);
            float4 b = sb4[jj];
            acc += a.x * b.x + a.y * b.y + a.z * b.z + a.w * b.w;
        }
        g_K[k][i] = acc;
        g_KTq[i][k] = __float2half(acc);
    } else {
        // 8 shifted reversed-u copies: g_uRq8[s][c][b][x] = uR(x + s)
        const int total8 = 8 * NCHUNK * B_DIM * 256;
        for (int idx = (blockIdx.x - 127) * 256 + tid; idx < total8;
             idx += (PGRID - 127) * 256) {
            int s = idx >> 19;
            int rem = idx & ((1 << 19) - 1);
            int c = rem >> 15;
            int b = (rem >> 8) & 127;
            int x = rem & 255;
            int q = x + s;
            float v = (q <= 127) ? u[(c * CHK + 127 - q) * B_DIM + b] : 0.0f;
            g_uRq8[s][c][b][x] = __float2half(v);
        }
    }
}

// ---------------------------------------------------------------------------
// chunk-end conv (fp32): E_j[b][i] = sum_{k<128} Kvec[k][i] * u[j*128+127-k][b]
// ---------------------------------------------------------------------------
__device__ __forceinline__ void mm_compute16(const float (*Ast)[68], const float (*Bs)[66],
                                             float2 acc[4][2], int ty, int tx) {
#pragma unroll
    for (int kk = 0; kk < 16; kk++) {
        float2 b0 = *reinterpret_cast<const float2*>(&Bs[kk][tx * 4]);
        float2 b1 = *reinterpret_cast<const float2*>(&Bs[kk][tx * 4 + 2]);
#pragma unroll
        for (int ii = 0; ii < 4; ii++) {
            float a = Ast[kk][ty * 4 + ii];
            float2 a2 = make_float2(a, a);
            ffma2(acc[ii][0], a2, b0);
            ffma2(acc[ii][1], a2, b1);
        }
    }
}

__global__ void k_etail(const float* __restrict__ u) {
    int j = blockIdx.z;
    int b0 = blockIdx.y * 64, i0 = blockIdx.x * 64;
    __shared__ float Ast[16][68];
    __shared__ float Bs[16][66];
    int tid = threadIdx.x, tx = tid & 15, ty = tid >> 4;
    float2 acc[4][2] = {};

    for (int k0 = 0; k0 < CHK; k0 += 16) {
#pragma unroll
        for (int p = 0; p < 4; p++) {
            int idx = p * 256 + tid;
            int kk = idx >> 6, bb = idx & 63;
            Ast[kk][bb] = u[(j * CHK + 127 - (k0 + kk)) * B_DIM + b0 + bb];
        }
#pragma unroll
        for (int p = 0; p < 4; p++) {
            int idx = p * 256 + tid;
            int kk = idx >> 6, ii = idx & 63;
            Bs[kk][ii] = g_K[k0 + kk][i0 + ii];
        }
        __syncthreads();
        mm_compute16(Ast, Bs, acc, ty, tx);
        __syncthreads();
    }
#pragma unroll
    for (int ii = 0; ii < 4; ii++) {
        float4 v = make_float4(acc[ii][0].x, acc[ii][0].y, acc[ii][1].x, acc[ii][1].y);
        *reinterpret_cast<float4*>(&g_E[j][b0 + ty * 4 + ii][i0 + tx * 4]) = v;
    }
}

// ---------------------------------------------------------------------------
// F precompute (parallel): F_j = E_j + E_{j-1} @ P128^T, j = 1..15
// grid (4 itile, 2 btile, 15 j)
// ---------------------------------------------------------------------------
__global__ void k_fprep() {
    int j = blockIdx.z + 1;
    int b0 = blockIdx.y * 64, i0 = blockIdx.x * 64;
    const float* __restrict__ A = &g_E[j - 1][0][0];
    const float* __restrict__ B = &g_P[CHK][0][0];

    __shared__ float Ast[16][68];
    __shared__ float Bs[16][66];
    int tid = threadIdx.x, tx = tid & 15, ty = tid >> 4;
    float2 acc[4][2] = {};

    for (int k0 = 0; k0 < N_DIM; k0 += 16) {
#pragma unroll
        for (int p = 0; p < 4; p++) {
            int idx = p * 256 + tid;
            int r = idx >> 4, kk = idx & 15;
            Ast[kk][r] = A[(b0 + r) * N_DIM + k0 + kk];
        }
#pragma unroll
        for (int p = 0; p < 4; p++) {
            int idx = p * 256 + tid;
            int ii = idx >> 4, kk = idx & 15;
            Bs[kk][ii] = B[(i0 + ii) * N_DIM + k0 + kk];
        }
        __syncthreads();
        mm_compute16(Ast, Bs, acc, ty, tx);
        __syncthreads();
    }
#pragma unroll
    for (int ii = 0; ii < 4; ii++) {
        int b = b0 + ty * 4 + ii;
        const float4 e = *reinterpret_cast<const float4*>(&g_E[j][b][i0 + tx * 4]);
        float4 v = make_float4(e.x + acc[ii][0].x, e.y + acc[ii][0].y,
                               e.z + acc[ii][1].x, e.w + acc[ii][1].y);
        *reinterpret_cast<float4*>(&g_F[j][b][i0 + tx * 4]) = v;
    }
}

// ---------------------------------------------------------------------------
// parity scan: two independent 7-step chains with T^2 = P256^T.
//   even: X_0 = E_0;  X_{2s}   = F_{2s}   + X_{2s-2} T^2   (s = 1..7)
//   odd:  X_1 = F_1;  X_{2s+1} = F_{2s+1} + X_{2s-1} T^2   (s = 1..6)
// 64 CTAs (32 per parity, each a 32b x 32i tile). P256 slice resident in smem.
// ---------------------------------------------------------------------------
#define SCAN_SMEM (256 * 34 * 4 + 32 * 260 * 4)
__global__ void __launch_bounds__(256, 1) k_scanx3() {
    extern __shared__ float sx[];
    float (*Psm)[34] = reinterpret_cast<float(*)[34]>(sx);             // [k 256][ir 32]
    float (*Xs)[260] = reinterpret_cast<float(*)[260]>(sx + 256 * 34); // [b 32][k 256]
    int tid = threadIdx.x;
    int par = blockIdx.x & 1;
    int tb = blockIdx.x >> 1;          // 0..31
    int b0 = (tb >> 3) * 32;
    int i0 = (tb & 7) * 32;

    // resident P256 slice: Psm[k][ir] = P256[i0+ir][k]
#pragma unroll
    for (int it = 0; it < 8; it++) {
        int e = it * 256 + tid;
        int ir = e >> 6, v = e & 63;
        float4 x = *reinterpret_cast<const float4*>(&g_P2[i0 + ir][v * 4]);
        Psm[v * 4 + 0][ir] = x.x;
        Psm[v * 4 + 1][ir] = x.y;
        Psm[v * 4 + 2][ir] = x.z;
        Psm[v * 4 + 3][ir] = x.w;
    }
    // init: even -> X_0 = E_0 (g_Xq[1]); odd -> X_1 = F_1 (g_Xq[2])
    {
        int r = tid >> 3, v = tid & 7;
        const float* src = (par == 0) ? &g_E[0][0][0] : &g_F[1][0][0];
        float4 x0 = *reinterpret_cast<const float4*>(src + (b0 + r) * N_DIM + i0 + v * 4);
        *reinterpret_cast<float4*>(&g_Xf[par][0][b0 + r][i0 + v * 4]) = x0;
        __half2 h0 = __floats2half2_rn(x0.x, x0.y);
        __half2 h1 = __floats2half2_rn(x0.z, x0.w);
        *reinterpret_cast<__half2*>(&g_Xq[1 + par][b0 + r][i0 + v * 4]) = h0;
        *reinterpret_cast<__half2*>(&g_Xq[1 + par][b0 + r][i0 + v * 4 + 2]) = h1;
    }
    gbar_on(&g_barctr2, XGRID);

    int ty = tid >> 3, tx = tid & 7;   // row 0..31, colgrp 0..7 (x4)
    for (int s = 1; s <= 7; s++) {
        int j = 2 * s + par;
        bool active = (j <= 14 + par) && (j <= 15) && ((par == 0) ? (j <= 14) : (j <= 13));
        if (active) {
            const float* src = &g_Xf[par][(s - 1) & 1][0][0];
#pragma unroll
            for (int it = 0; it < 8; it++) {
                int e = it * 256 + tid;
                int r = e >> 6, v = e & 63;
                float4 x = *reinterpret_cast<const float4*>(src + (b0 + r) * N_DIM + v * 4);
                *reinterpret_cast<float4*>(&Xs[r][v * 4]) = x;
            }
            __syncthreads();
            float2 c0 = make_float2(0.f, 0.f), c1 = make_float2(0.f, 0.f);
#pragma unroll 4
            for (int k = 0; k < 256; k++) {
                float2 p0 = *reinterpret_cast<const float2*>(&Psm[k][tx * 4]);
                float2 p1 = *reinterpret_cast<const float2*>(&Psm[k][tx * 4 + 2]);
                float a = Xs[ty][k];
                float2 a2 = make_float2(a, a);
                ffma2(c0, a2, p0);
                ffma2(c1, a2, p1);
            }
            float4 fj = *reinterpret_cast<const float4*>(&g_F[j][b0 + ty][i0 + tx * 4]);
            float4 xv = make_float4(fj.x + c0.x, fj.y + c0.y, fj.z + c1.x, fj.w + c1.y);
            *reinterpret_cast<float4*>(&g_Xf[par][s & 1][b0 + ty][i0 + tx * 4]) = xv;
            __half2 h0 = __floats2half2_rn(xv.x, xv.y);
            __half2 h1 = __floats2half2_rn(xv.z, xv.w);
            *reinterpret_cast<__half2*>(&g_Xq[j + 1][b0 + ty][i0 + tx * 4]) = h0;
            *reinterpret_cast<__half2*>(&g_Xq[j + 1][b0 + ty][i0 + tx * 4 + 2]) = h1;
        }
        gbar_on(&g_barctr2, XGRID * (unsigned)(s + 1));
    }
}

// ---------------------------------------------------------------------------
// fused mma kernel v5: fp16 single product, 4-deep cp.async ring, all-async
// staging, 2 CTAs per timestep (N-halves), K-chunk 32, zero-chunk skip, stcs.
// ---------------------------------------------------------------------------
#define FST 80          // smem row stride bytes (32 fp16 = 64B + 16 pad)
#define ST_B 10240
#define STAGE_B 20480
#define SMEM_FUSED (4 * STAGE_B)

__global__ void __launch_bounds__(256, 2) k_fused(float* __restrict__ out) {
    extern __shared__ char smbuf[];
    const uint32_t sb = smem_u32(smbuf);
    const int tid = threadIdx.x;
    const int lane = tid & 31, wid = tid >> 5;
    const int wm = wid & 3, wn = wid >> 2;        // 4 x 2 warp grid
    const int bx = blockIdx.x;
    const int r = bx >> 5;                        // 32 consecutive CTAs share P[r+1]
    const int c = (bx >> 1) & 15;
    const int bn = bx & 1;                        // N-half
    const int t = c * CHK + r;

    float acc[2][8][4];
#pragma unroll
    for (int ma = 0; ma < 2; ma++)
#pragma unroll
        for (int nb = 0; nb < 8; nb++)
#pragma unroll
            for (int q = 0; q < 4; q++) acc[ma][nb][q] = 0.f;

    const int nc = (r >> 5) + 1;                  // conv chunks
    const int nact = nc + ((c > 0) ? 8 : 0);      // + X chunks
    const int s8 = (127 - r) & 7;
    const int xbase = 127 - r - s8;               // 8-aligned

    auto stage = [&](int li) {
        int buf = li & 3;
        int kc = (li < nc) ? li : (li - nc + 4);
        uint32_t s0 = sb + buf * STAGE_B;
        if (kc < 4) {
            int x0 = xbase + kc * 32;
#pragma unroll
            for (int it = 0; it < 2; it++) {
                int e = it * 256 + tid;
                int row = e >> 2, v = e & 3;
                cp16(s0 + row * FST + v * 16, &g_uRq8[s8][c][row][x0 + v * 8]);
            }
#pragma unroll
            for (int it = 0; it < 2; it++) {
                int e = it * 256 + tid;
                int row = e >> 2, v = e & 3;
                cp16(s0 + ST_B + row * FST + v * 16, &g_KTq[bn * 128 + row][kc * 32 + v * 8]);
            }
        } else {
            int kb = (kc - 4) * 32;
#pragma unroll
            for (int it = 0; it < 2; it++) {
                int e = it * 256 + tid;
                int row = e >> 2, v = e & 3;
                cp16(s0 + row * FST + v * 16, &g_Xq[c][row][kb + v * 8]);
            }
#pragma unroll
            for (int it = 0; it < 2; it++) {
                int e = it * 256 + tid;
                int row = e >> 2, v = e & 3;
                cp16(s0 + ST_B + row * FST + v * 16, &g_Pq[r + 1][bn * 128 + row][kb + v * 8]);
            }
        }
        cp_commit();
    };

    auto compute = [&](int buf) {
        uint32_t s0 = sb + buf * STAGE_B;
        uint32_t aA = s0 + (wm * 32 + (lane & 15)) * FST + (lane >> 4) * 16;
        uint32_t aB = s0 + ST_B + (wn * 64 + (lane & 15)) * FST + (lane >> 4) * 16;
#pragma unroll
        for (int ks = 0; ks < 2; ks++) {
            uint32_t Ah[8];
#pragma unroll
            for (int ma = 0; ma < 2; ma++)
                ldsm4(&Ah[ma * 4], aA + ma * (16 * FST) + ks * 32);
#pragma unroll
            for (int pr = 0; pr < 4; pr++) {
                uint32_t bh[4];
                ldsm4(bh, aB + pr * (16 * FST) + ks * 32);
#pragma unroll
                for (int sub = 0; sub < 2; sub++) {
                    int nb = pr * 2 + sub;
#pragma unroll
                    for (int ma = 0; ma < 2; ma++)
                        mma_f16(acc[ma][nb], &Ah[ma * 4], bh[sub], bh[2 + sub]);
                }
            }
        }
    };

    if (0 < nact) stage(0);
    if (1 < nact) stage(1);
    if (2 < nact) stage(2);
#pragma unroll 1
    for (int li = 0; li < nact; li++) {
        int ahead = nact - 1 - li;
        if (ahead >= 2) cp_wait<2>();
        else if (ahead == 1) cp_wait<1>();
        else cp_wait<0>();
        __syncthreads();
        if (li + 3 < nact) stage(li + 3);
        compute(li & 3);
    }

    // epilogue: evict-first fp32 stores
    float* outt = out + (size_t)t * (B_DIM * N_DIM);
#pragma unroll
    for (int ma = 0; ma < 2; ma++) {
        int row = wm * 32 + ma * 16 + (lane >> 2);
#pragma unroll
        for (int nb = 0; nb < 8; nb++) {
            int col = bn * 128 + wn * 64 + nb * 8 + (lane & 3) * 2;
            __stcs(reinterpret_cast<float2*>(outt + row * 256 + col),
                   make_float2(acc[ma][nb][0], acc[ma][nb][1]));
            __stcs(reinterpret_cast<float2*>(outt + (row + 8) * 256 + col),
                   make_float2(acc[ma][nb][2], acc[ma][nb][3]));
        }
    }
}

// ---------------------------------------------------------------------------
extern "C" void kernel_launch(void* const* d_in, const int* in_sizes, int n_in,
                              void* d_out, int out_size) {
    const float* u  = (const float*)d_in[0];   // [L, B]
    const float* dA = (const float*)d_in[1];   // [N, N]
    const float* dB = (const float*)d_in[2];   // [N]
    float* out = (float*)d_out;                // [L, B, N]

    cudaFuncSetAttribute(k_fused, cudaFuncAttributeMaxDynamicSharedMemorySize, SMEM_FUSED);
    cudaFuncSetAttribute(k_scanx3, cudaFuncAttributeMaxDynamicSharedMemorySize, SCAN_SMEM);

    k_init<<<256, 256>>>(dA, dB);
    k_powerall<<<PGRID, 256>>>(dB, u);
    k_etail<<<dim3(4, 2, NCHUNK), 256>>>(u);
    k_fprep<<<dim3(4, 2, 15), 256>>>();
    k_scanx3<<<XGRID, 256, SCAN_SMEM>>>();
    k_fused<<<2 * L_DIM, 256, SMEM_FUSED>>>(out);
}

// round 10
// speedup vs baseline: 4.7565x; 1.0539x over previous
#include <cuda_runtime.h>
#include <cuda_fp16.h>
#include <cstdint>

// Problem constants
#define N_DIM 256
#define L_DIM 2048
#define B_DIM 128
#define CHK   128
#define NCHUNK 16
#define PGRID 296
#define POSTG 128

// ---------------------------------------------------------------------------
// Device global scratch
// ---------------------------------------------------------------------------
__device__ float g_P[CHK + 1][N_DIM][N_DIM];        // dA^p fp32, p = 1..128
__device__ float g_P2[N_DIM][N_DIM];                // dA^256 fp32 (T^2)
__device__ float g_PT[N_DIM][N_DIM];                // P128^T fp32
__device__ float g_K[CHK][N_DIM];                   // Kvec fp32
__device__ float g_E[NCHUNK][B_DIM][N_DIM];         // chunk-end conv values
__device__ float g_F[NCHUNK][B_DIM][N_DIM];         // F_j = E_j + E_{j-1} T
__device__ float g_Xf[2][2][B_DIM][N_DIM];          // fp32 X ping-pong per parity
__device__ float g_Ppart[256][4096];                // split-K partial tiles
__device__ unsigned g_tilecnt[256];                 // split-K arrival counters
__device__ __half g_Pq[CHK + 1][N_DIM][N_DIM];      // fp16 P
__device__ __half g_KTq[N_DIM][CHK];                // fp16 K transposed
__device__ __half g_uRq8[8][NCHUNK][B_DIM][256];    // 8 byte-shift copies of reversed u
__device__ __half g_Xq[NCHUNK][B_DIM][N_DIM];       // fp16 X_{c-1} (c>=1)
__device__ unsigned g_barctr;
__device__ unsigned g_barctr2;

// ---------------------------------------------------------------------------
// helpers
// ---------------------------------------------------------------------------
__device__ __forceinline__ void ffma2(float2& c, float2 a, float2 b) {
    asm("{\n\t"
        ".reg .b64 ra, rb, rc;\n\t"
        "mov.b64 ra, {%2, %3};\n\t"
        "mov.b64 rb, {%4, %5};\n\t"
        "mov.b64 rc, {%0, %1};\n\t"
        "fma.rn.f32x2 rc, ra, rb, rc;\n\t"
        "mov.b64 {%0, %1}, rc;\n\t"
        "}"
        : "+f"(c.x), "+f"(c.y)
        : "f"(a.x), "f"(a.y), "f"(b.x), "f"(b.y));
}

__device__ __forceinline__ uint32_t smem_u32(const void* p) {
    uint32_t a;
    asm("{ .reg .u64 t; cvta.to.shared.u64 t, %1; cvt.u32.u64 %0, t; }" : "=r"(a) : "l"(p));
    return a;
}

__device__ __forceinline__ void mma_f16(float d[4], const uint32_t a[4],
                                        uint32_t b0, uint32_t b1) {
    asm volatile(
        "mma.sync.aligned.m16n8k16.row.col.f32.f16.f16.f32 "
        "{%0,%1,%2,%3}, {%4,%5,%6,%7}, {%8,%9}, {%0,%1,%2,%3};"
        : "+f"(d[0]), "+f"(d[1]), "+f"(d[2]), "+f"(d[3])
        : "r"(a[0]), "r"(a[1]), "r"(a[2]), "r"(a[3]), "r"(b0), "r"(b1));
}

__device__ __forceinline__ void ldsm4(uint32_t* r, uint32_t addr) {
    asm volatile("ldmatrix.sync.aligned.m8n8.x4.shared.b16 {%0,%1,%2,%3}, [%4];"
                 : "=r"(r[0]), "=r"(r[1]), "=r"(r[2]), "=r"(r[3]) : "r"(addr));
}

__device__ __forceinline__ void cp16(uint32_t sdst, const void* gsrc) {
    asm volatile("cp.async.cg.shared.global [%0], [%1], 16;" :: "r"(sdst), "l"(gsrc));
}
__device__ __forceinline__ void cp_commit() {
    asm volatile("cp.async.commit_group;" ::: "memory");
}
template <int NW>
__device__ __forceinline__ void cp_wait() {
    asm volatile("cp.async.wait_group %0;" :: "n"(NW) : "memory");
}
__device__ __forceinline__ void cp_wait_ahead(int ahead) {
    if (ahead >= 2) cp_wait<2>();
    else if (ahead == 1) cp_wait<1>();
    else cp_wait<0>();
}

// grid-wide software barriers (monotonic counters; reset each replay in k_init)
__device__ __forceinline__ void gbar_on(unsigned* ctr, unsigned target) {
    __syncthreads();
    if (threadIdx.x == 0) {
        __threadfence();
        atomicAdd(ctr, 1u);
        unsigned v;
        do {
            asm volatile("ld.acquire.gpu.u32 %0, [%1];" : "=r"(v) : "l"(ctr));
        } while (v < target);
    }
    __syncthreads();
}

// ---------------------------------------------------------------------------
// init: P[1] = dA (+ fp16), K[0] = dB, counters reset
// ---------------------------------------------------------------------------
__global__ void k_init(const float* __restrict__ dA, const float* __restrict__ dB) {
    int idx = blockIdx.x * 256 + threadIdx.x;
    if (idx == 0) { g_barctr = 0u; g_barctr2 = 0u; }
    if (idx < 256) g_tilecnt[idx] = 0u;
    if (idx < N_DIM * N_DIM) {
        float x = dA[idx];
        (&g_P[1][0][0])[idx] = x;
        (&g_Pq[1][0][0])[idx] = __float2half(x);
    }
    if (idx < N_DIM) {
        g_K[0][idx] = dB[idx];
        g_KTq[idx][0] = __float2half(dB[idx]);
    }
}

// ---------------------------------------------------------------------------
// single-launch power chain with split-K on early phases; tail computes
// P256, P128^T, Kvec (fp32 + fp16T), and 8 shifted reversed-u fp16 copies.
// ---------------------------------------------------------------------------
__global__ void __launch_bounds__(256, 2) k_powerall(const float* __restrict__ dB,
                                                     const float* __restrict__ u) {
    __shared__ __align__(16) float As[4][64][20];
    __shared__ __align__(16) float Bs[4][16][68];
    __shared__ unsigned s_old;
    int tid = threadIdx.x, tx = tid & 15, ty = tid >> 4;

    // pipelined 64x64 tile over nks 16-wide K slices starting at slice ks0
    auto run_tile = [&](const float* __restrict__ A, const float* __restrict__ B,
                        int row0, int col0, int ks0, int nks, float2 acc[4][2]) {
        auto issue = [&](int kc) {
            int s = kc & 3, k0 = (ks0 + kc) * 16;
            {
                int row = tid >> 2, v = tid & 3;
                cp16(smem_u32(&As[s][row][v * 4]), &A[(row0 + row) * N_DIM + k0 + v * 4]);
            }
            {
                int row = tid >> 4, v = tid & 15;
                cp16(smem_u32(&Bs[s][row][v * 4]), &B[(k0 + row) * N_DIM + col0 + v * 4]);
            }
            cp_commit();
        };
#pragma unroll 1
        for (int p = 0; p < 3 && p < nks; p++) issue(p);
#pragma unroll 1
        for (int kc = 0; kc < nks; kc++) {
            cp_wait_ahead(nks - 1 - kc);
            __syncthreads();
            if (kc + 3 < nks) issue(kc + 3);
            int s = kc & 3;
#pragma unroll
            for (int kk4 = 0; kk4 < 4; kk4++) {
                float4 a4[4];
#pragma unroll
                for (int ii = 0; ii < 4; ii++)
                    a4[ii] = *reinterpret_cast<const float4*>(&As[s][ty * 4 + ii][kk4 * 4]);
#pragma unroll
                for (int q = 0; q < 4; q++) {
                    int kk = kk4 * 4 + q;
                    float2 b0 = *reinterpret_cast<const float2*>(&Bs[s][kk][tx * 4]);
                    float2 b1 = *reinterpret_cast<const float2*>(&Bs[s][kk][tx * 4 + 2]);
#pragma unroll
                    for (int ii = 0; ii < 4; ii++) {
                        float av = (q == 0) ? a4[ii].x : (q == 1) ? a4[ii].y
                                 : (q == 2) ? a4[ii].z : a4[ii].w;
                        float2 a2 = make_float2(av, av);
                        ffma2(acc[ii][0], a2, b0);
                        ffma2(acc[ii][1], a2, b1);
                    }
                }
            }
        }
        __syncthreads();
    };

    const int SPL[7] = {8, 8, 4, 2, 1, 1, 1};

    for (int ph = 0; ph < 7; ph++) {
        int m = 1 << ph;
        int sk = SPL[ph];
        int ntile = 16 * m;
        int nwork = ntile * sk;
        int nks = 16 / sk;
        for (int w = blockIdx.x; w < nwork; w += PGRID) {
            int tile = w / sk, slice = w - tile * sk;
            int j = (tile >> 4) + 1, ti = tile & 15;
            int row0 = (ti >> 2) * 64, col0 = (ti & 3) * 64;
            float2 acc[4][2] = {};
            run_tile(&g_P[j][0][0], &g_P[m][0][0], row0, col0, slice * nks, nks, acc);

            if (sk == 1) {
                float* C = &g_P[m + j][0][0];
                __half* Cq = &g_Pq[m + j][0][0];
#pragma unroll
                for (int ii = 0; ii < 4; ii++) {
                    int row = row0 + ty * 4 + ii, col = col0 + tx * 4;
                    float4 v = make_float4(acc[ii][0].x, acc[ii][0].y,
                                           acc[ii][1].x, acc[ii][1].y);
                    *reinterpret_cast<float4*>(&C[row * N_DIM + col]) = v;
                    *reinterpret_cast<__half2*>(&Cq[row * N_DIM + col]) =
                        __floats2half2_rn(v.x, v.y);
                    *reinterpret_cast<__half2*>(&Cq[row * N_DIM + col + 2]) =
                        __floats2half2_rn(v.z, v.w);
                }
            } else {
                // write partial
#pragma unroll
                for (int ii = 0; ii < 4; ii++) {
                    float4 v = make_float4(acc[ii][0].x, acc[ii][0].y,
                                           acc[ii][1].x, acc[ii][1].y);
                    *reinterpret_cast<float4*>(&g_Ppart[w][(ty * 4 + ii) * 64 + tx * 4]) = v;
                }
                __syncthreads();
                if (tid == 0) {
                    __threadfence();
                    s_old = atomicAdd(&g_tilecnt[tile], 1u);
                }
                __syncthreads();
                if (s_old == (unsigned)(sk - 1)) {
                    // deterministic last-arriver reduction (fixed s2 order)
                    float* C = &g_P[m + j][0][0];
                    __half* Cq = &g_Pq[m + j][0][0];
#pragma unroll
                    for (int ii = 0; ii < 4; ii++) {
                        float4 vs = make_float4(0.f, 0.f, 0.f, 0.f);
                        for (int s2 = 0; s2 < sk; s2++) {
                            float4 pv = __ldcg(reinterpret_cast<const float4*>(
                                &g_Ppart[tile * sk + s2][(ty * 4 + ii) * 64 + tx * 4]));
                            vs.x += pv.x; vs.y += pv.y; vs.z += pv.z; vs.w += pv.w;
                        }
                        int row = row0 + ty * 4 + ii, col = col0 + tx * 4;
                        *reinterpret_cast<float4*>(&C[row * N_DIM + col]) = vs;
                        *reinterpret_cast<__half2*>(&Cq[row * N_DIM + col]) =
                            __floats2half2_rn(vs.x, vs.y);
                        *reinterpret_cast<__half2*>(&Cq[row * N_DIM + col + 2]) =
                            __floats2half2_rn(vs.z, vs.w);
                    }
                    __syncthreads();
                    if (tid == 0) g_tilecnt[tile] = 0u;   // reset for next phase
                }
            }
        }
        gbar_on(&g_barctr, PGRID * (unsigned)(ph + 1));
    }

    // ---- tail (disjoint CTA ranges) ----
    int bx = blockIdx.x;
    if (bx < 16) {
        // P256 = P128 @ P128 (fp32)
        int row0 = (bx >> 2) * 64, col0 = (bx & 3) * 64;
        float2 acc[4][2] = {};
        run_tile(&g_P[CHK][0][0], &g_P[CHK][0][0], row0, col0, 0, 16, acc);
#pragma unroll
        for (int ii = 0; ii < 4; ii++) {
            int row = row0 + ty * 4 + ii, col = col0 + tx * 4;
            *reinterpret_cast<float4*>(&g_P2[row][col]) =
                make_float4(acc[ii][0].x, acc[ii][0].y, acc[ii][1].x, acc[ii][1].y);
        }
    } else if (bx < 143) {
        // K[k] = P[k] @ dB for k = bx - 15
        float* sDB = &As[0][0][0];
        sDB[tid] = dB[tid];
        __syncthreads();
        int k = bx - 15;
        int i = tid;
        const float4* row4 = reinterpret_cast<const float4*>(&g_P[k][i][0]);
        const float4* sb4 = reinterpret_cast<const float4*>(sDB);
        float acc = 0.0f;
#pragma unroll 8
        for (int jj = 0; jj < N_DIM / 4; jj++) {
            float4 a = __ldcg(&row4[jj]);
            float4 b = sb4[jj];
            acc += a.x * b.x + a.y * b.y + a.z * b.z + a.w * b.w;
        }
        g_K[k][i] = acc;
        g_KTq[i][k] = __float2half(acc);
    } else if (bx < 159) {
        // PT = P128^T
        int base = (bx - 143) * 4096 + tid * 16;
        for (int q = 0; q < 16; q++) {
            int e = base + q;
            int k = e >> 8, i = e & 255;
            (&g_PT[0][0])[e] = __ldcg(&g_P[CHK][i][k]);
        }
    } else {
        // 8 shifted reversed-u copies: g_uRq8[s][c][b][x] = uR(x + s)
        const int total8 = 8 * NCHUNK * B_DIM * 256;
        for (int idx = (bx - 159) * 256 + tid; idx < total8;
             idx += (PGRID - 159) * 256) {
            int s = idx >> 19;
            int rem = idx & ((1 << 19) - 1);
            int c = rem >> 15;
            int b = (rem >> 8) & 127;
            int x = rem & 255;
            int q = x + s;
            float v = (q <= 127) ? u[(c * CHK + 127 - q) * B_DIM + b] : 0.0f;
            g_uRq8[s][c][b][x] = __float2half(v);
        }
    }
}

// ---------------------------------------------------------------------------
// k_post: etail + fprep + parity-scan fused in one launch (grid barriers).
// 128 CTAs, 256 threads, dynamic smem (union of phase layouts).
// ---------------------------------------------------------------------------
#define POST_SMEM (256 * 34 * 4 + 32 * 260 * 4)

__global__ void __launch_bounds__(256, 1) k_post(const float* __restrict__ u) {
    extern __shared__ float sp[];
    int tid = threadIdx.x, tx = tid & 15, ty = tid >> 4;
    int bx = blockIdx.x;
    unsigned epoch = 0;

    // ================= phase 1: etail =================
    // E_j[b][i] = sum_k Kvec[k][i] * uR_j[k][b];  128 tiles, K=128 (8 slices)
    {
        int j = bx >> 3;
        int b0 = ((bx >> 2) & 1) * 64, i0 = (bx & 3) * 64;
        int t0 = j * CHK;
        float (*Ast)[16][68] = reinterpret_cast<float(*)[16][68]>(sp);
        float (*Bss)[16][68] = reinterpret_cast<float(*)[16][68]>(sp + 4 * 16 * 68);
        auto issue = [&](int kc) {
            int s = kc & 3, k0 = kc * 16;
            int kk = tid >> 4, v = tid & 15;
            cp16(smem_u32(&Ast[s][kk][v * 4]),
                 &u[(t0 + 127 - (k0 + kk)) * B_DIM + b0 + v * 4]);
            cp16(smem_u32(&Bss[s][kk][v * 4]), &g_K[k0 + kk][i0 + v * 4]);
            cp_commit();
        };
        issue(0); issue(1); issue(2);
        float2 acc[4][2] = {};
#pragma unroll 1
        for (int kc = 0; kc < 8; kc++) {
            cp_wait_ahead(7 - kc);
            __syncthreads();
            if (kc + 3 < 8) issue(kc + 3);
            int s = kc & 3;
#pragma unroll
            for (int kk = 0; kk < 16; kk++) {
                float2 b0v = *reinterpret_cast<const float2*>(&Bss[s][kk][tx * 4]);
                float2 b1v = *reinterpret_cast<const float2*>(&Bss[s][kk][tx * 4 + 2]);
#pragma unroll
                for (int ii = 0; ii < 4; ii++) {
                    float a = Ast[s][kk][ty * 4 + ii];
                    float2 a2 = make_float2(a, a);
                    ffma2(acc[ii][0], a2, b0v);
                    ffma2(acc[ii][1], a2, b1v);
                }
            }
        }
        __syncthreads();
#pragma unroll
        for (int ii = 0; ii < 4; ii++) {
            *reinterpret_cast<float4*>(&g_E[j][b0 + ty * 4 + ii][i0 + tx * 4]) =
                make_float4(acc[ii][0].x, acc[ii][0].y, acc[ii][1].x, acc[ii][1].y);
        }
    }
    gbar_on(&g_barctr2, POSTG * (++epoch));

    // ================= phase 2: fprep =================
    // F_j = E_j + E_{j-1} @ PT (NN, K=256, 16 slices); 120 tiles
    if (bx < 120) {
        int j = (bx >> 3) + 1;
        int b0 = ((bx >> 2) & 1) * 64, i0 = (bx & 3) * 64;
        const float* __restrict__ A = &g_E[j - 1][0][0];
        const float* __restrict__ B = &g_PT[0][0];
        float (*As)[64][20] = reinterpret_cast<float(*)[64][20]>(sp);
        float (*Bss)[16][68] = reinterpret_cast<float(*)[16][68]>(sp + 4 * 64 * 20);
        auto issue = [&](int kc) {
            int s = kc & 3, k0 = kc * 16;
            {
                int row = tid >> 2, v = tid & 3;
                cp16(smem_u32(&As[s][row][v * 4]), &A[(b0 + row) * N_DIM + k0 + v * 4]);
            }
            {
                int row = tid >> 4, v = tid & 15;
                cp16(smem_u32(&Bss[s][row][v * 4]), &B[(k0 + row) * N_DIM + i0 + v * 4]);
            }
            cp_commit();
        };
        issue(0); issue(1); issue(2);
        float2 acc[4][2] = {};
#pragma unroll 1
        for (int kc = 0; kc < 16; kc++) {
            cp_wait_ahead(15 - kc);
            __syncthreads();
            if (kc + 3 < 16) issue(kc + 3);
            int s = kc & 3;
#pragma unroll
            for (int kk4 = 0; kk4 < 4; kk4++) {
                float4 a4[4];
#pragma unroll
                for (int ii = 0; ii < 4; ii++)
                    a4[ii] = *reinterpret_cast<const float4*>(&As[s][ty * 4 + ii][kk4 * 4]);
#pragma unroll
                for (int q = 0; q < 4; q++) {
                    int kk = kk4 * 4 + q;
                    float2 b0v = *reinterpret_cast<const float2*>(&Bss[s][kk][tx * 4]);
                    float2 b1v = *reinterpret_cast<const float2*>(&Bss[s][kk][tx * 4 + 2]);
#pragma unroll
                    for (int ii = 0; ii < 4; ii++) {
                        float av = (q == 0) ? a4[ii].x : (q == 1) ? a4[ii].y
                                 : (q == 2) ? a4[ii].z : a4[ii].w;
                        float2 a2 = make_float2(av, av);
                        ffma2(acc[ii][0], a2, b0v);
                        ffma2(acc[ii][1], a2, b1v);
                    }
                }
            }
        }
        __syncthreads();
#pragma unroll
        for (int ii = 0; ii < 4; ii++) {
            int b = b0 + ty * 4 + ii;
            float4 e = *reinterpret_cast<const float4*>(&g_E[j][b][i0 + tx * 4]);
            *reinterpret_cast<float4*>(&g_F[j][b][i0 + tx * 4]) =
                make_float4(e.x + acc[ii][0].x, e.y + acc[ii][0].y,
                            e.z + acc[ii][1].x, e.w + acc[ii][1].y);
        }
    }
    gbar_on(&g_barctr2, POSTG * (++epoch));

    // ================= phase 3: parity scan =================
    // even: X_0 = E_0; X_{2s} = F_{2s} + X_{2s-2} T^2
    // odd:  X_1 = F_1; X_{2s+1} = F_{2s+1} + X_{2s-1} T^2
    {
        bool sact = bx < 64;
        int par = bx & 1, tb = bx >> 1;
        int b0 = (tb >> 3) * 32, i0 = (tb & 7) * 32;
        float (*Psm)[34] = reinterpret_cast<float(*)[34]>(sp);
        float (*Xs)[260] = reinterpret_cast<float(*)[260]>(sp + 256 * 34);

        if (sact) {
            // resident P256 slice: Psm[k][ir] = P256[i0+ir][k]
#pragma unroll
            for (int it = 0; it < 8; it++) {
                int e = it * 256 + tid;
                int ir = e >> 6, v = e & 63;
                float4 x = *reinterpret_cast<const float4*>(&g_P2[i0 + ir][v * 4]);
                Psm[v * 4 + 0][ir] = x.x;
                Psm[v * 4 + 1][ir] = x.y;
                Psm[v * 4 + 2][ir] = x.z;
                Psm[v * 4 + 3][ir] = x.w;
            }
            int r = tid >> 3, v = tid & 7;
            const float* src = (par == 0) ? &g_E[0][0][0] : &g_F[1][0][0];
            float4 x0 = *reinterpret_cast<const float4*>(src + (b0 + r) * N_DIM + i0 + v * 4);
            *reinterpret_cast<float4*>(&g_Xf[par][0][b0 + r][i0 + v * 4]) = x0;
            *reinterpret_cast<__half2*>(&g_Xq[1 + par][b0 + r][i0 + v * 4]) =
                __floats2half2_rn(x0.x, x0.y);
            *reinterpret_cast<__half2*>(&g_Xq[1 + par][b0 + r][i0 + v * 4 + 2]) =
                __floats2half2_rn(x0.z, x0.w);
        }
        gbar_on(&g_barctr2, POSTG * (++epoch));

        int ty2 = tid >> 3, tx2 = tid & 7;
        for (int s = 1; s <= 7; s++) {
            int j = 2 * s + par;
            bool active = sact && ((par == 0) ? (s <= 7) : (s <= 6));
            if (active) {
                const float* src = &g_Xf[par][(s - 1) & 1][0][0];
#pragma unroll
                for (int it = 0; it < 8; it++) {
                    int e = it * 256 + tid;
                    int r = e >> 6, v = e & 63;
                    float4 x = *reinterpret_cast<const float4*>(src + (b0 + r) * N_DIM + v * 4);
                    *reinterpret_cast<float4*>(&Xs[r][v * 4]) = x;
                }
                __syncthreads();
                float2 c0 = make_float2(0.f, 0.f), c1 = make_float2(0.f, 0.f);
#pragma unroll 4
                for (int k = 0; k < 256; k++) {
                    float2 p0 = *reinterpret_cast<const float2*>(&Psm[k][tx2 * 4]);
                    float2 p1 = *reinterpret_cast<const float2*>(&Psm[k][tx2 * 4 + 2]);
                    float a = Xs[ty2][k];
                    float2 a2 = make_float2(a, a);
                    ffma2(c0, a2, p0);
                    ffma2(c1, a2, p1);
                }
                float4 fj = *reinterpret_cast<const float4*>(&g_F[j][b0 + ty2][i0 + tx2 * 4]);
                float4 xv = make_float4(fj.x + c0.x, fj.y + c0.y, fj.z + c1.x, fj.w + c1.y);
                *reinterpret_cast<float4*>(&g_Xf[par][s & 1][b0 + ty2][i0 + tx2 * 4]) = xv;
                *reinterpret_cast<__half2*>(&g_Xq[j + 1][b0 + ty2][i0 + tx2 * 4]) =
                    __floats2half2_rn(xv.x, xv.y);
                *reinterpret_cast<__half2*>(&g_Xq[j + 1][b0 + ty2][i0 + tx2 * 4 + 2]) =
                    __floats2half2_rn(xv.z, xv.w);
            }
            gbar_on(&g_barctr2, POSTG * (++epoch));
        }
    }
}

// ---------------------------------------------------------------------------
// fused mma kernel: fp16 single product, 4-deep cp.async ring, all-async
// staging, 2 CTAs per timestep (N-halves), K-chunk 32, zero-chunk skip, stcs.
// ---------------------------------------------------------------------------
#define FST 80          // smem row stride bytes (32 fp16 = 64B + 16 pad)
#define ST_B 10240
#define STAGE_B 20480
#define SMEM_FUSED (4 * STAGE_B)

__global__ void __launch_bounds__(256, 2) k_fused(float* __restrict__ out) {
    extern __shared__ char smbuf[];
    const uint32_t sb = smem_u32(smbuf);
    const int tid = threadIdx.x;
    const int lane = tid & 31, wid = tid >> 5;
    const int wm = wid & 3, wn = wid >> 2;        // 4 x 2 warp grid
    const int bx = blockIdx.x;
    const int r = bx >> 5;                        // 32 consecutive CTAs share P[r+1]
    const int c = (bx >> 1) & 15;
    const int bn = bx & 1;                        // N-half
    const int t = c * CHK + r;

    float acc[2][8][4];
#pragma unroll
    for (int ma = 0; ma < 2; ma++)
#pragma unroll
        for (int nb = 0; nb < 8; nb++)
#pragma unroll
            for (int q = 0; q < 4; q++) acc[ma][nb][q] = 0.f;

    const int nc = (r >> 5) + 1;                  // conv chunks
    const int nact = nc + ((c > 0) ? 8 : 0);      // + X chunks
    const int s8 = (127 - r) & 7;
    const int xbase = 127 - r - s8;               // 8-aligned

    auto stage = [&](int li) {
        int buf = li & 3;
        int kc = (li < nc) ? li : (li - nc + 4);
        uint32_t s0 = sb + buf * STAGE_B;
        if (kc < 4) {
            int x0 = xbase + kc * 32;
#pragma unroll
            for (int it = 0; it < 2; it++) {
                int e = it * 256 + tid;
                int row = e >> 2, v = e & 3;
                cp16(s0 + row * FST + v * 16, &g_uRq8[s8][c][row][x0 + v * 8]);
            }
#pragma unroll
            for (int it = 0; it < 2; it++) {
                int e = it * 256 + tid;
                int row = e >> 2, v = e & 3;
                cp16(s0 + ST_B + row * FST + v * 16, &g_KTq[bn * 128 + row][kc * 32 + v * 8]);
            }
        } else {
            int kb = (kc - 4) * 32;
#pragma unroll
            for (int it = 0; it < 2; it++) {
                int e = it * 256 + tid;
                int row = e >> 2, v = e & 3;
                cp16(s0 + row * FST + v * 16, &g_Xq[c][row][kb + v * 8]);
            }
#pragma unroll
            for (int it = 0; it < 2; it++) {
                int e = it * 256 + tid;
                int row = e >> 2, v = e & 3;
                cp16(s0 + ST_B + row * FST + v * 16, &g_Pq[r + 1][bn * 128 + row][kb + v * 8]);
            }
        }
        cp_commit();
    };

    auto compute = [&](int buf) {
        uint32_t s0 = sb + buf * STAGE_B;
        uint32_t aA = s0 + (wm * 32 + (lane & 15)) * FST + (lane >> 4) * 16;
        uint32_t aB = s0 + ST_B + (wn * 64 + (lane & 15)) * FST + (lane >> 4) * 16;
#pragma unroll
        for (int ks = 0; ks < 2; ks++) {
            uint32_t Ah[8];
#pragma unroll
            for (int ma = 0; ma < 2; ma++)
                ldsm4(&Ah[ma * 4], aA + ma * (16 * FST) + ks * 32);
#pragma unroll
            for (int pr = 0; pr < 4; pr++) {
                uint32_t bh[4];
                ldsm4(bh, aB + pr * (16 * FST) + ks * 32);
#pragma unroll
                for (int sub = 0; sub < 2; sub++) {
                    int nb = pr * 2 + sub;
#pragma unroll
                    for (int ma = 0; ma < 2; ma++)
                        mma_f16(acc[ma][nb], &Ah[ma * 4], bh[sub], bh[2 + sub]);
                }
            }
        }
    };

    if (0 < nact) stage(0);
    if (1 < nact) stage(1);
    if (2 < nact) stage(2);
#pragma unroll 1
    for (int li = 0; li < nact; li++) {
        cp_wait_ahead(nact - 1 - li);
        __syncthreads();
        if (li + 3 < nact) stage(li + 3);
        compute(li & 3);
    }

    // epilogue: evict-first fp32 stores
    float* outt = out + (size_t)t * (B_DIM * N_DIM);
#pragma unroll
    for (int ma = 0; ma < 2; ma++) {
        int row = wm * 32 + ma * 16 + (lane >> 2);
#pragma unroll
        for (int nb = 0; nb < 8; nb++) {
            int col = bn * 128 + wn * 64 + nb * 8 + (lane & 3) * 2;
            __stcs(reinterpret_cast<float2*>(outt + row * 256 + col),
                   make_float2(acc[ma][nb][0], acc[ma][nb][1]));
            __stcs(reinterpret_cast<float2*>(outt + (row + 8) * 256 + col),
                   make_float2(acc[ma][nb][2], acc[ma][nb][3]));
        }
    }
}

// ---------------------------------------------------------------------------
extern "C" void kernel_launch(void* const* d_in, const int* in_sizes, int n_in,
                              void* d_out, int out_size) {
    const float* u  = (const float*)d_in[0];   // [L, B]
    const float* dA = (const float*)d_in[1];   // [N, N]
    const float* dB = (const float*)d_in[2];   // [N]
    float* out = (float*)d_out;                // [L, B, N]

    cudaFuncSetAttribute(k_fused, cudaFuncAttributeMaxDynamicSharedMemorySize, SMEM_FUSED);
    cudaFuncSetAttribute(k_post, cudaFuncAttributeMaxDynamicSharedMemorySize, POST_SMEM);

    k_init<<<256, 256>>>(dA, dB);
    k_powerall<<<PGRID, 256>>>(dB, u);
    k_post<<<POSTG, 256, POST_SMEM>>>(u);
    k_fused<<<2 * L_DIM, 256, SMEM_FUSED>>>(out);
}